// round 1
// baseline (speedup 1.0000x reference)
#include <cuda_runtime.h>
#include <math.h>

// ---------------- problem constants ----------------
#define T_TOK 4096          // B*S
#define HDIM  2048
#define NEXP  8
#define CAP   1536          // int(2*2048*1.5*2/8)
#define NHID  5120          // 1024 (imp) + 2048 (r) + 2048 (u)

// output layout (flat float32): disp, comb, router_probs, aux_loss, importance
#define DISP_OFF 0
#define COMB_OFF 50331648
#define PROB_OFF 100663296
#define AUX_OFF  100696064
#define IMP_OFF  100696065

// ---------------- device scratch (no cudaMalloc allowed) ----------------
__device__ float  g_hidden[(size_t)T_TOK * NHID];   // 84 MB
__device__ float  g_logits[T_TOK * 17];             // [imp, r0..7, u0..7]
__device__ int    g_top_i[T_TOK];                   // i0 | (i1<<8)
__device__ float2 g_top_p[T_TOK];                   // normalized top-2 probs
__device__ int    g_occ0;                           // bitmask: expert seen in round 0

// ---------------- zero-fill disp+comb + reset occ0 ----------------
__global__ void zero_kernel(float4* __restrict__ out, unsigned int n4) {
    unsigned int i = blockIdx.x * blockDim.x + threadIdx.x;
    unsigned int stride = gridDim.x * blockDim.x;
    float4 z = make_float4(0.f, 0.f, 0.f, 0.f);
    for (; i < n4; i += stride) out[i] = z;
    if (blockIdx.x == 0 && threadIdx.x == 0) g_occ0 = 0;
}

// ---------------- GEMM1: hidden = relu(X @ [Wi1|Wr1|Wu1] + bias) ----------------
// M=4096, N=5120 (block-mapped to the 3 weights), K=2048, fp32.
#define BM 128
#define BN 128
#define BK 16

__global__ __launch_bounds__(256, 2)
void gemm1_kernel(const float* __restrict__ X,
                  const float* __restrict__ Wi1, const float* __restrict__ bi1,
                  const float* __restrict__ Wr1, const float* __restrict__ br1,
                  const float* __restrict__ Wu1, const float* __restrict__ bu1)
{
    __shared__ float As[BK][BM];   // transposed A tile
    __shared__ float Bs[BK][BN];

    const int tid = threadIdx.x;
    const int bm  = blockIdx.y;
    const int bn  = blockIdx.x;
    const int n0  = bn * BN;

    const float* W; const float* bias; int ldb, nloc;
    if (n0 < 1024)      { W = Wi1; bias = bi1; ldb = 1024; nloc = n0; }
    else if (n0 < 3072) { W = Wr1; bias = br1; ldb = 2048; nloc = n0 - 1024; }
    else                { W = Wu1; bias = bu1; ldb = 2048; nloc = n0 - 3072; }

    const float* Aptr = X + (size_t)(bm * BM) * HDIM;
    const float* Bptr = W + nloc;

    const int arow = tid >> 2;          // 0..63  (two rows: arow, arow+64)
    const int acol = (tid & 3) << 2;    // 0,4,8,12
    const int brow = tid >> 5;          // 0..7   (two rows: brow, brow+8)
    const int bcol = (tid & 31) << 2;   // 0..124

    const int tx = tid & 15;
    const int ty = tid >> 4;

    float acc[8][8];
#pragma unroll
    for (int i = 0; i < 8; i++)
#pragma unroll
        for (int j = 0; j < 8; j++) acc[i][j] = 0.f;

    // prefetch tile 0
    float4 ra0 = *(const float4*)(Aptr + (size_t)arow * HDIM + acol);
    float4 ra1 = *(const float4*)(Aptr + (size_t)(arow + 64) * HDIM + acol);
    float4 rb0 = *(const float4*)(Bptr + (size_t)brow * ldb + bcol);
    float4 rb1 = *(const float4*)(Bptr + (size_t)(brow + 8) * ldb + bcol);

    const int NT = HDIM / BK;   // 128
    for (int kt = 0; kt < NT; kt++) {
        // deposit prefetched tile
        As[acol + 0][arow]      = ra0.x;
        As[acol + 1][arow]      = ra0.y;
        As[acol + 2][arow]      = ra0.z;
        As[acol + 3][arow]      = ra0.w;
        As[acol + 0][arow + 64] = ra1.x;
        As[acol + 1][arow + 64] = ra1.y;
        As[acol + 2][arow + 64] = ra1.z;
        As[acol + 3][arow + 64] = ra1.w;
        *(float4*)&Bs[brow][bcol]     = rb0;
        *(float4*)&Bs[brow + 8][bcol] = rb1;
        __syncthreads();

        if (kt + 1 < NT) {
            const int kk = (kt + 1) * BK;
            ra0 = *(const float4*)(Aptr + (size_t)arow * HDIM + kk + acol);
            ra1 = *(const float4*)(Aptr + (size_t)(arow + 64) * HDIM + kk + acol);
            rb0 = *(const float4*)(Bptr + (size_t)(kk + brow) * ldb + bcol);
            rb1 = *(const float4*)(Bptr + (size_t)(kk + brow + 8) * ldb + bcol);
        }

#pragma unroll
        for (int k = 0; k < BK; k++) {
            float a[8], b[8];
            *(float4*)&a[0] = *(const float4*)&As[k][ty * 8];
            *(float4*)&a[4] = *(const float4*)&As[k][ty * 8 + 4];
            *(float4*)&b[0] = *(const float4*)&Bs[k][tx * 8];
            *(float4*)&b[4] = *(const float4*)&Bs[k][tx * 8 + 4];
#pragma unroll
            for (int i = 0; i < 8; i++)
#pragma unroll
                for (int j = 0; j < 8; j++)
                    acc[i][j] = fmaf(a[i], b[j], acc[i][j]);
        }
        __syncthreads();
    }

    // epilogue: bias + relu -> g_hidden (row-major 4096 x 5120)
#pragma unroll
    for (int i = 0; i < 8; i++) {
        const int m = bm * BM + ty * 8 + i;
        float* dst = g_hidden + (size_t)m * NHID + n0 + tx * 8;
#pragma unroll
        for (int j = 0; j < 8; j++) {
            float c = acc[i][j] + bias[nloc + tx * 8 + j];
            dst[j] = fmaxf(c, 0.f);
        }
    }
}

// ---------------- GEMM2: per-token second layers (warp per token) ----------------
__global__ void gemm2_kernel(const float* __restrict__ Wi2, const float* __restrict__ bi2,
                             const float* __restrict__ Wr2, const float* __restrict__ br2,
                             const float* __restrict__ Wu2, const float* __restrict__ bu2)
{
    const int gw   = (blockIdx.x * blockDim.x + threadIdx.x) >> 5;
    const int lane = threadIdx.x & 31;
    if (gw >= T_TOK) return;
    const float* h = g_hidden + (size_t)gw * NHID;

    float acc[17];
#pragma unroll
    for (int j = 0; j < 17; j++) acc[j] = 0.f;

    // importance head: h[0:1024] . Wi2
#pragma unroll
    for (int it = 0; it < 8; it++) {
        const int k = it * 128 + lane * 4;
        float4 hv = *(const float4*)(h + k);
        float4 wv = *(const float4*)(Wi2 + k);
        acc[0] += hv.x * wv.x + hv.y * wv.y + hv.z * wv.z + hv.w * wv.w;
    }
    // imp-router head: h[1024:3072] @ Wr2 (2048x8, row-major)
#pragma unroll 4
    for (int it = 0; it < 16; it++) {
        const int k = it * 128 + lane * 4;
        float4 hv = *(const float4*)(h + 1024 + k);
        const float* wr = Wr2 + (size_t)k * 8;
        float hq[4] = {hv.x, hv.y, hv.z, hv.w};
#pragma unroll
        for (int q = 0; q < 4; q++) {
            float4 w0 = *(const float4*)(wr + q * 8);
            float4 w1 = *(const float4*)(wr + q * 8 + 4);
            acc[1] += hq[q] * w0.x; acc[2] += hq[q] * w0.y;
            acc[3] += hq[q] * w0.z; acc[4] += hq[q] * w0.w;
            acc[5] += hq[q] * w1.x; acc[6] += hq[q] * w1.y;
            acc[7] += hq[q] * w1.z; acc[8] += hq[q] * w1.w;
        }
    }
    // unimp-router head: h[3072:5120] @ Wu2
#pragma unroll 4
    for (int it = 0; it < 16; it++) {
        const int k = it * 128 + lane * 4;
        float4 hv = *(const float4*)(h + 3072 + k);
        const float* wu = Wu2 + (size_t)k * 8;
        float hq[4] = {hv.x, hv.y, hv.z, hv.w};
#pragma unroll
        for (int q = 0; q < 4; q++) {
            float4 w0 = *(const float4*)(wu + q * 8);
            float4 w1 = *(const float4*)(wu + q * 8 + 4);
            acc[9]  += hq[q] * w0.x; acc[10] += hq[q] * w0.y;
            acc[11] += hq[q] * w0.z; acc[12] += hq[q] * w0.w;
            acc[13] += hq[q] * w1.x; acc[14] += hq[q] * w1.y;
            acc[15] += hq[q] * w1.z; acc[16] += hq[q] * w1.w;
        }
    }

    // butterfly reduction across lanes (fixed order -> deterministic)
#pragma unroll
    for (int j = 0; j < 17; j++)
#pragma unroll
        for (int off = 16; off > 0; off >>= 1)
            acc[j] += __shfl_xor_sync(0xffffffffu, acc[j], off);

    if (lane == 0) {
        float* o = g_logits + gw * 17;
        o[0] = acc[0] + bi2[0];
#pragma unroll
        for (int e = 0; e < NEXP; e++) o[1 + e] = acc[1 + e] + br2[e];
#pragma unroll
        for (int e = 0; e < NEXP; e++) o[9 + e] = acc[9 + e] + bu2[e];
    }
}

// ---------------- router: sigmoid, select, softmax, top-2 ----------------
__global__ void router_kernel(float* __restrict__ out)
{
    const int t = blockIdx.x * blockDim.x + threadIdx.x;
    if (t >= T_TOK) return;
    const float* l = g_logits + t * 17;

    const float l0  = l[0];
    const float imp = 1.f / (1.f + expf(-l0));
    out[IMP_OFF + t] = imp;
    const bool mask = imp > 0.5f;

    float lg[NEXP];
#pragma unroll
    for (int e = 0; e < NEXP; e++) lg[e] = mask ? l[1 + e] : l[9 + e];

    float m = lg[0];
#pragma unroll
    for (int e = 1; e < NEXP; e++) m = fmaxf(m, lg[e]);
    float p[NEXP], s = 0.f;
#pragma unroll
    for (int e = 0; e < NEXP; e++) { p[e] = expf(lg[e] - m); s += p[e]; }
#pragma unroll
    for (int e = 0; e < NEXP; e++) {
        p[e] = p[e] / s;                       // division to match jax softmax rounding
        out[PROB_OFF + (size_t)t * NEXP + e] = p[e];
    }

    // top-2, ties -> lower index (matches jax.lax.top_k)
    int i0 = 0; float p0 = p[0];
#pragma unroll
    for (int e = 1; e < NEXP; e++) if (p[e] > p0) { p0 = p[e]; i0 = e; }
    int i1 = -1; float p1 = -1.f;
#pragma unroll
    for (int e = 0; e < NEXP; e++) if (e != i0 && p[e] > p1) { p1 = p[e]; i1 = e; }

    const float sn = p0 + p1;
    g_top_i[t] = i0 | (i1 << 8);
    g_top_p[t] = make_float2(p0 / sn, p1 / sn);
    atomicOr(&g_occ0, 1 << i0);   // idempotent -> deterministic
}

// ---------------- scatter: dispatch/combine entries ----------------
__global__ void scatter_kernel(float* __restrict__ out)
{
    const int t = blockIdx.x * blockDim.x + threadIdx.x;
    if (t >= T_TOK) return;
    const int ii = g_top_i[t];
    const int i0 = ii & 255;
    const int i1 = (ii >> 8) & 255;
    const float2 pp = g_top_p[t];
    const int occ = g_occ0;

    // round 0: count==0 -> position 0, always under capacity
    size_t base0 = (size_t)(t * NEXP + i0) * CAP;
    out[DISP_OFF + base0] = 1.f;
    out[COMB_OFF + base0] = pp.x;
    // round 1: position = occ0[i1] (0 or 1), always under capacity
    const int pos1 = (occ >> i1) & 1;
    size_t base1 = (size_t)(t * NEXP + i1) * CAP + pos1;
    out[DISP_OFF + base1] = 1.f;
    out[COMB_OFF + base1] = pp.y;
}

// ---------------- finalize: aux_loss (single block, deterministic tree) ----------------
__global__ void finalize_kernel(float* __restrict__ out)
{
    const int tid = threadIdx.x;
    __shared__ float sr[NEXP][256];
    __shared__ float si[NEXP][256];

    float rl[NEXP], il[NEXP];
#pragma unroll
    for (int e = 0; e < NEXP; e++) { rl[e] = 0.f; il[e] = 0.f; }

    for (int t = tid; t < T_TOK; t += 256) {
        const float l0 = g_logits[t * 17];
        const float imp = 1.f / (1.f + expf(-l0));
        const float mv  = imp > 0.5f ? 1.f : 0.f;
#pragma unroll
        for (int e = 0; e < NEXP; e++) {
            const float pe = out[PROB_OFF + (size_t)t * NEXP + e];
            rl[e] += pe;
            il[e] += pe * mv;
        }
    }
#pragma unroll
    for (int e = 0; e < NEXP; e++) { sr[e][tid] = rl[e]; si[e][tid] = il[e]; }
    __syncthreads();
    for (int s = 128; s > 0; s >>= 1) {
        if (tid < s) {
#pragma unroll
            for (int e = 0; e < NEXP; e++) {
                sr[e][tid] += sr[e][tid + s];
                si[e][tid] += si[e][tid + s];
            }
        }
        __syncthreads();
    }
    if (tid == 0) {
        const float EPS = 1e-9f;
        float entropy_loss = 0.f;
        float imp_sum[NEXP], tot = 0.f;
#pragma unroll
        for (int e = 0; e < NEXP; e++) {
            const float rppe = sr[e][0] / (float)T_TOK;
            entropy_loss += rppe * logf(rppe * (float)NEXP + EPS);
            imp_sum[e] = si[e][0] + EPS;
            tot += imp_sum[e];
        }
        float imp_entropy = 0.f;
#pragma unroll
        for (int e = 0; e < NEXP; e++) {
            const float ipe = imp_sum[e] / tot;
            imp_entropy -= ipe * logf(ipe + EPS);
        }
        out[AUX_OFF] = entropy_loss - 0.1f * (imp_entropy / logf((float)NEXP));
    }
}

// ---------------- launch ----------------
extern "C" void kernel_launch(void* const* d_in, const int* in_sizes, int n_in,
                              void* d_out, int out_size)
{
    const float* x   = (const float*)d_in[0];
    const float* Wi1 = (const float*)d_in[1];
    const float* bi1 = (const float*)d_in[2];
    const float* Wi2 = (const float*)d_in[3];
    const float* bi2 = (const float*)d_in[4];
    const float* Wr1 = (const float*)d_in[5];
    const float* br1 = (const float*)d_in[6];
    const float* Wr2 = (const float*)d_in[7];
    const float* br2 = (const float*)d_in[8];
    const float* Wu1 = (const float*)d_in[9];
    const float* bu1 = (const float*)d_in[10];
    const float* Wu2 = (const float*)d_in[11];
    const float* bu2 = (const float*)d_in[12];
    float* out = (float*)d_out;

    // 1) zero disp+comb (402 MB) + reset occ0
    zero_kernel<<<2048, 256>>>((float4*)out, (unsigned int)(PROB_OFF / 4));
    // 2) big fused GEMM -> hidden
    dim3 g1(NHID / BN, T_TOK / BM);
    gemm1_kernel<<<g1, 256>>>(x, Wi1, bi1, Wr1, br1, Wu1, bu1);
    // 3) second-layer heads -> logits
    gemm2_kernel<<<T_TOK / 8, 256>>>(Wi2, bi2, Wr2, br2, Wu2, bu2);
    // 4) router decisions
    router_kernel<<<T_TOK / 256, 256>>>(out);
    // 5) dispatch/combine scatter + aux loss
    scatter_kernel<<<T_TOK / 256, 256>>>(out);
    finalize_kernel<<<1, 256>>>(out);
}

// round 2
// speedup vs baseline: 1.0018x; 1.0018x over previous
#include <cuda_runtime.h>
#include <math.h>

// ---------------- problem constants ----------------
#define T_TOK 4096          // B*S
#define HDIM  2048
#define NEXP  8
#define CAP   1536          // int(2*2048*1.5*2/8)
#define NHID  5120          // 1024 (imp) + 2048 (r) + 2048 (u)

// output layout (flat float32): disp, comb, router_probs, aux_loss, importance
#define DISP_OFF 0
#define COMB_OFF 50331648
#define PROB_OFF 100663296
#define AUX_OFF  100696064
#define IMP_OFF  100696065

// ---------------- device scratch (no cudaMalloc allowed) ----------------
__device__ float  g_hidden[(size_t)T_TOK * NHID];   // 84 MB
__device__ float  g_logits[T_TOK * 17];             // [imp, r0..7, u0..7]
__device__ int    g_top_i[T_TOK];                   // i0 | (i1<<8)
__device__ float2 g_top_p[T_TOK];                   // normalized top-2 probs
__device__ int    g_occ0;                           // bitmask: expert seen in round 0

// ---------------- zero-fill disp+comb + reset occ0 ----------------
__global__ void zero_kernel(float4* __restrict__ out, unsigned int n4) {
    unsigned int i = blockIdx.x * blockDim.x + threadIdx.x;
    unsigned int stride = gridDim.x * blockDim.x;
    float4 z = make_float4(0.f, 0.f, 0.f, 0.f);
    for (; i < n4; i += stride) out[i] = z;
    if (blockIdx.x == 0 && threadIdx.x == 0) g_occ0 = 0;
}

// ---------------- GEMM1: hidden = relu(X @ [Wi1|Wr1|Wu1] + bias) ----------------
// M=4096, N=5120 (block-mapped to the 3 weights), K=2048, fp32.
#define BM 128
#define BN 128
#define BK 16

__global__ __launch_bounds__(256, 2)
void gemm1_kernel(const float* __restrict__ X,
                  const float* __restrict__ Wi1, const float* __restrict__ bi1,
                  const float* __restrict__ Wr1, const float* __restrict__ br1,
                  const float* __restrict__ Wu1, const float* __restrict__ bu1)
{
    __shared__ float As[BK][BM];   // transposed A tile
    __shared__ float Bs[BK][BN];

    const int tid = threadIdx.x;
    const int bm  = blockIdx.y;
    const int bn  = blockIdx.x;
    const int n0  = bn * BN;

    const float* W; const float* bias; int ldb, nloc;
    if (n0 < 1024)      { W = Wi1; bias = bi1; ldb = 1024; nloc = n0; }
    else if (n0 < 3072) { W = Wr1; bias = br1; ldb = 2048; nloc = n0 - 1024; }
    else                { W = Wu1; bias = bu1; ldb = 2048; nloc = n0 - 3072; }

    const float* Aptr = X + (size_t)(bm * BM) * HDIM;
    const float* Bptr = W + nloc;

    const int arow = tid >> 2;          // 0..63  (two rows: arow, arow+64)
    const int acol = (tid & 3) << 2;    // 0,4,8,12
    const int brow = tid >> 5;          // 0..7   (two rows: brow, brow+8)
    const int bcol = (tid & 31) << 2;   // 0..124

    const int tx = tid & 15;
    const int ty = tid >> 4;

    float acc[8][8];
#pragma unroll
    for (int i = 0; i < 8; i++)
#pragma unroll
        for (int j = 0; j < 8; j++) acc[i][j] = 0.f;

    // prefetch tile 0
    float4 ra0 = *(const float4*)(Aptr + (size_t)arow * HDIM + acol);
    float4 ra1 = *(const float4*)(Aptr + (size_t)(arow + 64) * HDIM + acol);
    float4 rb0 = *(const float4*)(Bptr + (size_t)brow * ldb + bcol);
    float4 rb1 = *(const float4*)(Bptr + (size_t)(brow + 8) * ldb + bcol);

    const int NT = HDIM / BK;   // 128
    for (int kt = 0; kt < NT; kt++) {
        // deposit prefetched tile
        As[acol + 0][arow]      = ra0.x;
        As[acol + 1][arow]      = ra0.y;
        As[acol + 2][arow]      = ra0.z;
        As[acol + 3][arow]      = ra0.w;
        As[acol + 0][arow + 64] = ra1.x;
        As[acol + 1][arow + 64] = ra1.y;
        As[acol + 2][arow + 64] = ra1.z;
        As[acol + 3][arow + 64] = ra1.w;
        *(float4*)&Bs[brow][bcol]     = rb0;
        *(float4*)&Bs[brow + 8][bcol] = rb1;
        __syncthreads();

        if (kt + 1 < NT) {
            const int kk = (kt + 1) * BK;
            ra0 = *(const float4*)(Aptr + (size_t)arow * HDIM + kk + acol);
            ra1 = *(const float4*)(Aptr + (size_t)(arow + 64) * HDIM + kk + acol);
            rb0 = *(const float4*)(Bptr + (size_t)(kk + brow) * ldb + bcol);
            rb1 = *(const float4*)(Bptr + (size_t)(kk + brow + 8) * ldb + bcol);
        }

#pragma unroll
        for (int k = 0; k < BK; k++) {
            float a[8], b[8];
            *(float4*)&a[0] = *(const float4*)&As[k][ty * 8];
            *(float4*)&a[4] = *(const float4*)&As[k][ty * 8 + 4];
            *(float4*)&b[0] = *(const float4*)&Bs[k][tx * 8];
            *(float4*)&b[4] = *(const float4*)&Bs[k][tx * 8 + 4];
#pragma unroll
            for (int i = 0; i < 8; i++)
#pragma unroll
                for (int j = 0; j < 8; j++)
                    acc[i][j] = fmaf(a[i], b[j], acc[i][j]);
        }
        __syncthreads();
    }

    // epilogue: bias + relu -> g_hidden (row-major 4096 x 5120)
#pragma unroll
    for (int i = 0; i < 8; i++) {
        const int m = bm * BM + ty * 8 + i;
        float* dst = g_hidden + (size_t)m * NHID + n0 + tx * 8;
#pragma unroll
        for (int j = 0; j < 8; j++) {
            float c = acc[i][j] + bias[nloc + tx * 8 + j];
            dst[j] = fmaxf(c, 0.f);
        }
    }
}

// ---------------- GEMM2: per-token second layers (warp per token) ----------------
__global__ void gemm2_kernel(const float* __restrict__ Wi2, const float* __restrict__ bi2,
                             const float* __restrict__ Wr2, const float* __restrict__ br2,
                             const float* __restrict__ Wu2, const float* __restrict__ bu2)
{
    const int gw   = (blockIdx.x * blockDim.x + threadIdx.x) >> 5;
    const int lane = threadIdx.x & 31;
    if (gw >= T_TOK) return;
    const float* h = g_hidden + (size_t)gw * NHID;

    float acc[17];
#pragma unroll
    for (int j = 0; j < 17; j++) acc[j] = 0.f;

    // importance head: h[0:1024] . Wi2
#pragma unroll
    for (int it = 0; it < 8; it++) {
        const int k = it * 128 + lane * 4;
        float4 hv = *(const float4*)(h + k);
        float4 wv = *(const float4*)(Wi2 + k);
        acc[0] += hv.x * wv.x + hv.y * wv.y + hv.z * wv.z + hv.w * wv.w;
    }
    // imp-router head: h[1024:3072] @ Wr2 (2048x8, row-major)
#pragma unroll 4
    for (int it = 0; it < 16; it++) {
        const int k = it * 128 + lane * 4;
        float4 hv = *(const float4*)(h + 1024 + k);
        const float* wr = Wr2 + (size_t)k * 8;
        float hq[4] = {hv.x, hv.y, hv.z, hv.w};
#pragma unroll
        for (int q = 0; q < 4; q++) {
            float4 w0 = *(const float4*)(wr + q * 8);
            float4 w1 = *(const float4*)(wr + q * 8 + 4);
            acc[1] += hq[q] * w0.x; acc[2] += hq[q] * w0.y;
            acc[3] += hq[q] * w0.z; acc[4] += hq[q] * w0.w;
            acc[5] += hq[q] * w1.x; acc[6] += hq[q] * w1.y;
            acc[7] += hq[q] * w1.z; acc[8] += hq[q] * w1.w;
        }
    }
    // unimp-router head: h[3072:5120] @ Wu2
#pragma unroll 4
    for (int it = 0; it < 16; it++) {
        const int k = it * 128 + lane * 4;
        float4 hv = *(const float4*)(h + 3072 + k);
        const float* wu = Wu2 + (size_t)k * 8;
        float hq[4] = {hv.x, hv.y, hv.z, hv.w};
#pragma unroll
        for (int q = 0; q < 4; q++) {
            float4 w0 = *(const float4*)(wu + q * 8);
            float4 w1 = *(const float4*)(wu + q * 8 + 4);
            acc[9]  += hq[q] * w0.x; acc[10] += hq[q] * w0.y;
            acc[11] += hq[q] * w0.z; acc[12] += hq[q] * w0.w;
            acc[13] += hq[q] * w1.x; acc[14] += hq[q] * w1.y;
            acc[15] += hq[q] * w1.z; acc[16] += hq[q] * w1.w;
        }
    }

    // butterfly reduction across lanes (fixed order -> deterministic)
#pragma unroll
    for (int j = 0; j < 17; j++)
#pragma unroll
        for (int off = 16; off > 0; off >>= 1)
            acc[j] += __shfl_xor_sync(0xffffffffu, acc[j], off);

    if (lane == 0) {
        float* o = g_logits + gw * 17;
        o[0] = acc[0] + bi2[0];
#pragma unroll
        for (int e = 0; e < NEXP; e++) o[1 + e] = acc[1 + e] + br2[e];
#pragma unroll
        for (int e = 0; e < NEXP; e++) o[9 + e] = acc[9 + e] + bu2[e];
    }
}

// ---------------- router: sigmoid, select, softmax, top-2 ----------------
__global__ void router_kernel(float* __restrict__ out)
{
    const int t = blockIdx.x * blockDim.x + threadIdx.x;
    if (t >= T_TOK) return;
    const float* l = g_logits + t * 17;

    const float l0  = l[0];
    const float imp = 1.f / (1.f + expf(-l0));
    out[IMP_OFF + t] = imp;
    const bool mask = imp > 0.5f;

    float lg[NEXP];
#pragma unroll
    for (int e = 0; e < NEXP; e++) lg[e] = mask ? l[1 + e] : l[9 + e];

    float m = lg[0];
#pragma unroll
    for (int e = 1; e < NEXP; e++) m = fmaxf(m, lg[e]);
    float p[NEXP], s = 0.f;
#pragma unroll
    for (int e = 0; e < NEXP; e++) { p[e] = expf(lg[e] - m); s += p[e]; }
#pragma unroll
    for (int e = 0; e < NEXP; e++) {
        p[e] = p[e] / s;                       // division to match jax softmax rounding
        out[PROB_OFF + (size_t)t * NEXP + e] = p[e];
    }

    // top-2, ties -> lower index (matches jax.lax.top_k)
    int i0 = 0; float p0 = p[0];
#pragma unroll
    for (int e = 1; e < NEXP; e++) if (p[e] > p0) { p0 = p[e]; i0 = e; }
    int i1 = -1; float p1 = -1.f;
#pragma unroll
    for (int e = 0; e < NEXP; e++) if (e != i0 && p[e] > p1) { p1 = p[e]; i1 = e; }

    const float sn = p0 + p1;
    g_top_i[t] = i0 | (i1 << 8);
    g_top_p[t] = make_float2(p0 / sn, p1 / sn);
    atomicOr(&g_occ0, 1 << i0);   // idempotent -> deterministic
}

// ---------------- scatter: dispatch/combine entries ----------------
__global__ void scatter_kernel(float* __restrict__ out)
{
    const int t = blockIdx.x * blockDim.x + threadIdx.x;
    if (t >= T_TOK) return;
    const int ii = g_top_i[t];
    const int i0 = ii & 255;
    const int i1 = (ii >> 8) & 255;
    const float2 pp = g_top_p[t];
    const int occ = g_occ0;

    // round 0: count==0 -> position 0, always under capacity
    size_t base0 = (size_t)(t * NEXP + i0) * CAP;
    out[DISP_OFF + base0] = 1.f;
    out[COMB_OFF + base0] = pp.x;
    // round 1: position = occ0[i1] (0 or 1), always under capacity
    const int pos1 = (occ >> i1) & 1;
    size_t base1 = (size_t)(t * NEXP + i1) * CAP + pos1;
    out[DISP_OFF + base1] = 1.f;
    out[COMB_OFF + base1] = pp.y;
}

// ---------------- finalize: aux_loss (single block, deterministic tree) ----------------
__global__ void finalize_kernel(float* __restrict__ out)
{
    const int tid = threadIdx.x;
    __shared__ float sr[NEXP][256];
    __shared__ float si[NEXP][256];

    float rl[NEXP], il[NEXP];
#pragma unroll
    for (int e = 0; e < NEXP; e++) { rl[e] = 0.f; il[e] = 0.f; }

    for (int t = tid; t < T_TOK; t += 256) {
        const float l0 = g_logits[t * 17];
        const float imp = 1.f / (1.f + expf(-l0));
        const float mv  = imp > 0.5f ? 1.f : 0.f;
#pragma unroll
        for (int e = 0; e < NEXP; e++) {
            const float pe = out[PROB_OFF + (size_t)t * NEXP + e];
            rl[e] += pe;
            il[e] += pe * mv;
        }
    }
#pragma unroll
    for (int e = 0; e < NEXP; e++) { sr[e][tid] = rl[e]; si[e][tid] = il[e]; }
    __syncthreads();
    for (int s = 128; s > 0; s >>= 1) {
        if (tid < s) {
#pragma unroll
            for (int e = 0; e < NEXP; e++) {
                sr[e][tid] += sr[e][tid + s];
                si[e][tid] += si[e][tid + s];
            }
        }
        __syncthreads();
    }
    if (tid == 0) {
        const float EPS = 1e-9f;
        float entropy_loss = 0.f;
        float imp_sum[NEXP], tot = 0.f;
#pragma unroll
        for (int e = 0; e < NEXP; e++) {
            const float rppe = sr[e][0] / (float)T_TOK;
            entropy_loss += rppe * logf(rppe * (float)NEXP + EPS);
            imp_sum[e] = si[e][0] + EPS;
            tot += imp_sum[e];
        }
        float imp_entropy = 0.f;
#pragma unroll
        for (int e = 0; e < NEXP; e++) {
            const float ipe = imp_sum[e] / tot;
            imp_entropy -= ipe * logf(ipe + EPS);
        }
        out[AUX_OFF] = entropy_loss - 0.1f * (imp_entropy / logf((float)NEXP));
    }
}

// ---------------- launch ----------------
extern "C" void kernel_launch(void* const* d_in, const int* in_sizes, int n_in,
                              void* d_out, int out_size)
{
    const float* x   = (const float*)d_in[0];
    const float* Wi1 = (const float*)d_in[1];
    const float* bi1 = (const float*)d_in[2];
    const float* Wi2 = (const float*)d_in[3];
    const float* bi2 = (const float*)d_in[4];
    const float* Wr1 = (const float*)d_in[5];
    const float* br1 = (const float*)d_in[6];
    const float* Wr2 = (const float*)d_in[7];
    const float* br2 = (const float*)d_in[8];
    const float* Wu1 = (const float*)d_in[9];
    const float* bu1 = (const float*)d_in[10];
    const float* Wu2 = (const float*)d_in[11];
    const float* bu2 = (const float*)d_in[12];
    float* out = (float*)d_out;

    // 1) zero disp+comb (402 MB) + reset occ0
    zero_kernel<<<2048, 256>>>((float4*)out, (unsigned int)(PROB_OFF / 4));
    // 2) big fused GEMM -> hidden
    dim3 g1(NHID / BN, T_TOK / BM);
    gemm1_kernel<<<g1, 256>>>(x, Wi1, bi1, Wr1, br1, Wu1, bu1);
    // 3) second-layer heads -> logits
    gemm2_kernel<<<T_TOK / 8, 256>>>(Wi2, bi2, Wr2, br2, Wu2, bu2);
    // 4) router decisions
    router_kernel<<<T_TOK / 256, 256>>>(out);
    // 5) dispatch/combine scatter + aux loss
    scatter_kernel<<<T_TOK / 256, 256>>>(out);
    finalize_kernel<<<1, 256>>>(out);
}

// round 4
// speedup vs baseline: 1.5946x; 1.5919x over previous
#include <cuda_runtime.h>
#include <cuda_bf16.h>
#include <math.h>
#include <stdint.h>

#define T_TOK 4096
#define HDIM  2048
#define NEXP  8
#define CAP   1536
#define NHID  5120

#define DISP_OFF 0
#define COMB_OFF 50331648
#define PROB_OFF 100663296
#define AUX_OFF  100696064
#define IMP_OFF  100696065

#define TAU 3e-4f
#define MAXFIX 64

// ---------------- device scratch ----------------
__device__ float  g_hidden[(size_t)T_TOK * NHID];
__device__ float  g_logits[T_TOK * 17];
__device__ int    g_top_i[T_TOK];
__device__ float2 g_top_p[T_TOK];
__device__ int    g_occ0;
__device__ __nv_bfloat16 g_Xhi[(size_t)T_TOK * HDIM];
__device__ __nv_bfloat16 g_Xlo[(size_t)T_TOK * HDIM];
__device__ __nv_bfloat16 g_Whi[(size_t)NHID * HDIM];   // [n][k]
__device__ __nv_bfloat16 g_Wlo[(size_t)NHID * HDIM];
__device__ int    g_fix_count;
__device__ int    g_fix_list[MAXFIX];
__device__ float  g_fix_part[MAXFIX * 20 * 17];

// ---------------- helpers ----------------
__device__ __forceinline__ uint32_t smem_u32(const void* p) {
    uint32_t a;
    asm("{ .reg .u64 t; cvta.to.shared.u64 t, %1; cvt.u32.u64 %0, t; }" : "=r"(a) : "l"(p));
    return a;
}
#define SWZ(o) ((o) ^ (((o) >> 3) & 0x70))
#define CP_ASYNC16(dst, src) asm volatile("cp.async.cg.shared.global [%0], [%1], 16;" :: "r"(dst), "l"(src))
#define CP_COMMIT() asm volatile("cp.async.commit_group;" ::: "memory")
#define CP_WAIT(n)  asm volatile("cp.async.wait_group %0;" :: "n"(n) : "memory")

__device__ __forceinline__ void ldsm4(uint32_t& r0, uint32_t& r1, uint32_t& r2, uint32_t& r3, uint32_t addr) {
    asm volatile("ldmatrix.sync.aligned.m8n8.x4.shared.b16 {%0,%1,%2,%3}, [%4];"
        : "=r"(r0), "=r"(r1), "=r"(r2), "=r"(r3) : "r"(addr));
}
__device__ __forceinline__ void mma_bf16(float* d, uint32_t a0, uint32_t a1, uint32_t a2, uint32_t a3,
                                         uint32_t b0, uint32_t b1) {
    asm volatile("mma.sync.aligned.m16n8k16.row.col.f32.bf16.bf16.f32 "
        "{%0,%1,%2,%3}, {%4,%5,%6,%7}, {%8,%9}, {%0,%1,%2,%3};"
        : "+f"(d[0]), "+f"(d[1]), "+f"(d[2]), "+f"(d[3])
        : "r"(a0), "r"(a1), "r"(a2), "r"(a3), "r"(b0), "r"(b1));
}

// ---------------- zero-fill ----------------
__global__ void zero_kernel(float4* __restrict__ out, unsigned int n4) {
    unsigned int i = blockIdx.x * blockDim.x + threadIdx.x;
    unsigned int st = gridDim.x * blockDim.x;
    float4 z = make_float4(0.f, 0.f, 0.f, 0.f);
    for (; i < n4; i += st) out[i] = z;
    if (blockIdx.x == 0 && threadIdx.x == 0) { g_occ0 = 0; g_fix_count = 0; }
}

// ---------------- bf16 hi/lo split ----------------
__device__ __forceinline__ void split1(float x, unsigned short& h, unsigned short& l) {
    __nv_bfloat16 hb = __float2bfloat16_rn(x);
    __nv_bfloat16 lb = __float2bfloat16_rn(x - __bfloat162float(hb));
    h = *(unsigned short*)&hb; l = *(unsigned short*)&lb;
}

__global__ void split_x_kernel(const float4* __restrict__ X) {
    const unsigned int n4 = (unsigned int)((size_t)T_TOK * HDIM / 4);
    unsigned int i = blockIdx.x * blockDim.x + threadIdx.x;
    unsigned int st = gridDim.x * blockDim.x;
    for (; i < n4; i += st) {
        float4 v = X[i];
        ushort4 ph, pl;
        split1(v.x, ph.x, pl.x); split1(v.y, ph.y, pl.y);
        split1(v.z, ph.z, pl.z); split1(v.w, ph.w, pl.w);
        *(ushort4*)(g_Xhi + (size_t)i * 4) = ph;
        *(ushort4*)(g_Xlo + (size_t)i * 4) = pl;
    }
}

__global__ void split_w_kernel(const float* __restrict__ Wi1,
                               const float* __restrict__ Wr1,
                               const float* __restrict__ Wu1) {
    __shared__ float tile[32][33];
    const int tx = threadIdx.x, ty = threadIdx.y;
    const int nb = blockIdx.x * 32, kb = blockIdx.y * 32;
    const float* W; int nl, ld;
    if (nb < 1024)      { W = Wi1; nl = nb;        ld = 1024; }
    else if (nb < 3072) { W = Wr1; nl = nb - 1024; ld = 2048; }
    else                { W = Wu1; nl = nb - 3072; ld = 2048; }
#pragma unroll
    for (int r = 0; r < 4; r++)
        tile[ty + 8 * r][tx] = W[(size_t)(kb + ty + 8 * r) * ld + nl + tx];
    __syncthreads();
#pragma unroll
    for (int r = 0; r < 4; r++) {
        const int n = ty + 8 * r;
        unsigned short h, l;
        split1(tile[tx][n], h, l);
        size_t o = (size_t)(nb + n) * HDIM + kb + tx;
        *(unsigned short*)(g_Whi + o) = h;
        *(unsigned short*)(g_Wlo + o) = l;
    }
}

// ---------------- GEMM1 via mma.sync bf16 (3-product hi/lo) ----------------
// block 128x128, BK=64 halves (128B rows, XOR-128 swizzle), 3-stage cp.async.
#define BKH   64
#define STG   32768            // (128+128)*64*2 bytes per stage
#define NSTG  3
#define SMEM_GEMM (NSTG * STG) // 96 KB
#define KT_TOTAL 96            // 3 * 2048 / 64

__device__ __forceinline__ void g1_load_stage(uint32_t sbase, int slot, int kt, int bm, int bn, int tid) {
    const int sec = kt >> 5;
    const int k0 = (kt & 31) * BKH;
    const __nv_bfloat16* Ap = (sec == 2) ? g_Xlo : g_Xhi;
    const __nv_bfloat16* Bp = (sec == 1) ? g_Wlo : g_Whi;
    uint32_t sA = sbase + slot * STG;
    uint32_t sB = sA + 16384;
#pragma unroll
    for (int it = 0; it < 4; it++) {
        int seg = it * 256 + tid;
        int row = seg >> 3, ks = seg & 7;
        CP_ASYNC16(sA + SWZ(row * 128 + ks * 16),
                   Ap + (size_t)(bm * 128 + row) * HDIM + k0 + ks * 8);
    }
#pragma unroll
    for (int it = 0; it < 4; it++) {
        int seg = it * 256 + tid;
        int row = seg >> 3, ks = seg & 7;
        CP_ASYNC16(sB + SWZ(row * 128 + ks * 16),
                   Bp + (size_t)(bn * 128 + row) * HDIM + k0 + ks * 8);
    }
    CP_COMMIT();
}

__global__ __launch_bounds__(256, 1)
void gemm1_mma_kernel(const float* __restrict__ bi1,
                      const float* __restrict__ br1,
                      const float* __restrict__ bu1) {
    extern __shared__ char smem[];
    __shared__ float bias_s[128];
    const uint32_t sbase = smem_u32(smem);
    const int tid = threadIdx.x, wid = tid >> 5, lane = tid & 31;
    const int wm = wid & 3, wn = wid >> 2;         // 4 m-warps x 2 n-warps
    const int bn = blockIdx.x, bm = blockIdx.y;
    const int n0 = bn * 128;

    if (tid < 128) {
        const float* bias; int nl;
        if (n0 < 1024)      { bias = bi1; nl = n0; }
        else if (n0 < 3072) { bias = br1; nl = n0 - 1024; }
        else                { bias = bu1; nl = n0 - 3072; }
        bias_s[tid] = bias[nl + tid];
    }

    float d[2][8][4];
#pragma unroll
    for (int i = 0; i < 2; i++)
#pragma unroll
        for (int j = 0; j < 8; j++)
#pragma unroll
            for (int c = 0; c < 4; c++) d[i][j][c] = 0.f;

    g1_load_stage(sbase, 0, 0, bm, bn, tid);
    g1_load_stage(sbase, 1, 1, bm, bn, tid);

    const int lrow = lane & 15;
    const int lcol16 = (lane >> 4) * 16;

    for (int kt = 0; kt < KT_TOTAL; kt++) {
        if (kt + 2 < KT_TOTAL) { CP_WAIT(1); } else { CP_WAIT(0); }
        __syncthreads();
        if (kt + 2 < KT_TOTAL) g1_load_stage(sbase, (kt + 2) % NSTG, kt + 2, bm, bn, tid);

        const int slot = kt % NSTG;
        const uint32_t sA = sbase + slot * STG;
        const uint32_t sB = sA + 16384;
#pragma unroll
        for (int ks = 0; ks < 4; ks++) {
            uint32_t a[2][4];
#pragma unroll
            for (int im = 0; im < 2; im++) {
                int row = wm * 32 + im * 16 + lrow;
                ldsm4(a[im][0], a[im][1], a[im][2], a[im][3],
                      sA + SWZ(row * 128 + ks * 32 + lcol16));
            }
            uint32_t bfr[8][2];
#pragma unroll
            for (int ib = 0; ib < 4; ib++) {
                int row = wn * 64 + ib * 16 + lrow;
                uint32_t r0, r1, r2, r3;
                ldsm4(r0, r1, r2, r3, sB + SWZ(row * 128 + ks * 32 + lcol16));
                bfr[2 * ib][0] = r0;     bfr[2 * ib][1] = r2;
                bfr[2 * ib + 1][0] = r1; bfr[2 * ib + 1][1] = r3;
            }
#pragma unroll
            for (int im = 0; im < 2; im++)
#pragma unroll
                for (int jn = 0; jn < 8; jn++)
                    mma_bf16(d[im][jn], a[im][0], a[im][1], a[im][2], a[im][3],
                             bfr[jn][0], bfr[jn][1]);
        }
        __syncthreads();
    }

    // epilogue: bias + relu -> g_hidden
    const int r0 = lane >> 2;
    const int c0 = (lane & 3) * 2;
#pragma unroll
    for (int im = 0; im < 2; im++) {
        const int mg = bm * 128 + wm * 32 + im * 16;
#pragma unroll
        for (int jn = 0; jn < 8; jn++) {
            const int nl = wn * 64 + jn * 8 + c0;
            const float b0 = bias_s[nl], b1 = bias_s[nl + 1];
            float2 v0 = make_float2(fmaxf(d[im][jn][0] + b0, 0.f), fmaxf(d[im][jn][1] + b1, 0.f));
            float2 v1 = make_float2(fmaxf(d[im][jn][2] + b0, 0.f), fmaxf(d[im][jn][3] + b1, 0.f));
            *(float2*)(g_hidden + (size_t)(mg + r0) * NHID + n0 + nl) = v0;
            *(float2*)(g_hidden + (size_t)(mg + r0 + 8) * NHID + n0 + nl) = v1;
        }
    }
}

// ---------------- GEMM2: warp per token ----------------
__global__ void gemm2_kernel(const float* __restrict__ Wi2, const float* __restrict__ bi2,
                             const float* __restrict__ Wr2, const float* __restrict__ br2,
                             const float* __restrict__ Wu2, const float* __restrict__ bu2) {
    const int gw = (blockIdx.x * blockDim.x + threadIdx.x) >> 5;
    const int lane = threadIdx.x & 31;
    if (gw >= T_TOK) return;
    const float* h = g_hidden + (size_t)gw * NHID;
    float acc[17];
#pragma unroll
    for (int j = 0; j < 17; j++) acc[j] = 0.f;
#pragma unroll
    for (int it = 0; it < 8; it++) {
        const int k = it * 128 + lane * 4;
        float4 hv = *(const float4*)(h + k);
        float4 wv = *(const float4*)(Wi2 + k);
        acc[0] += hv.x * wv.x + hv.y * wv.y + hv.z * wv.z + hv.w * wv.w;
    }
#pragma unroll 4
    for (int it = 0; it < 16; it++) {
        const int k = it * 128 + lane * 4;
        float4 hv = *(const float4*)(h + 1024 + k);
        const float* wr = Wr2 + (size_t)k * 8;
        float hq[4] = {hv.x, hv.y, hv.z, hv.w};
#pragma unroll
        for (int q = 0; q < 4; q++) {
            float4 w0 = *(const float4*)(wr + q * 8);
            float4 w1 = *(const float4*)(wr + q * 8 + 4);
            acc[1] += hq[q] * w0.x; acc[2] += hq[q] * w0.y; acc[3] += hq[q] * w0.z; acc[4] += hq[q] * w0.w;
            acc[5] += hq[q] * w1.x; acc[6] += hq[q] * w1.y; acc[7] += hq[q] * w1.z; acc[8] += hq[q] * w1.w;
        }
    }
#pragma unroll 4
    for (int it = 0; it < 16; it++) {
        const int k = it * 128 + lane * 4;
        float4 hv = *(const float4*)(h + 3072 + k);
        const float* wu = Wu2 + (size_t)k * 8;
        float hq[4] = {hv.x, hv.y, hv.z, hv.w};
#pragma unroll
        for (int q = 0; q < 4; q++) {
            float4 w0 = *(const float4*)(wu + q * 8);
            float4 w1 = *(const float4*)(wu + q * 8 + 4);
            acc[9]  += hq[q] * w0.x; acc[10] += hq[q] * w0.y; acc[11] += hq[q] * w0.z; acc[12] += hq[q] * w0.w;
            acc[13] += hq[q] * w1.x; acc[14] += hq[q] * w1.y; acc[15] += hq[q] * w1.z; acc[16] += hq[q] * w1.w;
        }
    }
#pragma unroll
    for (int j = 0; j < 17; j++)
#pragma unroll
        for (int off = 16; off > 0; off >>= 1)
            acc[j] += __shfl_xor_sync(0xffffffffu, acc[j], off);
    if (lane == 0) {
        float* o = g_logits + gw * 17;
        o[0] = acc[0] + bi2[0];
#pragma unroll
        for (int e = 0; e < NEXP; e++) o[1 + e] = acc[1 + e] + br2[e];
#pragma unroll
        for (int e = 0; e < NEXP; e++) o[9 + e] = acc[9 + e] + bu2[e];
    }
}

// ---------------- flag borderline tokens ----------------
__global__ void flag_kernel() {
    const int t = blockIdx.x * blockDim.x + threadIdx.x;
    if (t >= T_TOK) return;
    const float* l = g_logits + t * 17;
    const float l0 = l[0];
    bool flag = fabsf(l0) < TAU;
    const bool mask = l0 > 0.f;
    float lg[NEXP];
#pragma unroll
    for (int e = 0; e < NEXP; e++) lg[e] = mask ? l[1 + e] : l[9 + e];
    float v1 = -1e30f, v2 = -1e30f, v3 = -1e30f;
#pragma unroll
    for (int e = 0; e < NEXP; e++) {
        float v = lg[e];
        if (v > v1)      { v3 = v2; v2 = v1; v1 = v; }
        else if (v > v2) { v3 = v2; v2 = v; }
        else if (v > v3) { v3 = v; }
    }
    if (v1 - v2 < TAU || v2 - v3 < TAU) flag = true;
    if (flag) {
        int idx = atomicAdd(&g_fix_count, 1);
        if (idx < MAXFIX) g_fix_list[idx] = t;
    }
}

// ---------------- exact fp32 recompute for flagged tokens ----------------
__global__ void fixup1_kernel(const float* __restrict__ X,
                              const float* __restrict__ Wi1, const float* __restrict__ bi1,
                              const float* __restrict__ Wr1, const float* __restrict__ br1,
                              const float* __restrict__ Wu1, const float* __restrict__ bu1,
                              const float* __restrict__ Wi2,
                              const float* __restrict__ Wr2,
                              const float* __restrict__ Wu2) {
    const int fi = blockIdx.x;
    int cnt = g_fix_count; if (cnt > MAXFIX) cnt = MAXFIX;
    if (fi >= cnt) return;
    const int t = g_fix_list[fi];
    const int n = blockIdx.y * 256 + threadIdx.x;
    __shared__ float xs[HDIM];
    __shared__ float red[17][257];
    for (int k = threadIdx.x; k < HDIM; k += 256) xs[k] = X[(size_t)t * HDIM + k];
    __syncthreads();

    const float* W; const float* b; int nl, ld;
    if (n < 1024)      { W = Wi1; b = bi1; nl = n;        ld = 1024; }
    else if (n < 3072) { W = Wr1; b = br1; nl = n - 1024; ld = 2048; }
    else               { W = Wu1; b = bu1; nl = n - 3072; ld = 2048; }
    float acc = 0.f;
    for (int k = 0; k < HDIM; k++) acc = fmaf(xs[k], W[(size_t)k * ld + nl], acc);
    float hval = fmaxf(acc + b[nl], 0.f);

    float part[17];
#pragma unroll
    for (int j = 0; j < 17; j++) part[j] = 0.f;
    if (n < 1024) part[0] = hval * Wi2[n];
    else if (n < 3072) {
        const float* w = Wr2 + (size_t)(n - 1024) * 8;
#pragma unroll
        for (int e = 0; e < NEXP; e++) part[1 + e] = hval * w[e];
    } else {
        const float* w = Wu2 + (size_t)(n - 3072) * 8;
#pragma unroll
        for (int e = 0; e < NEXP; e++) part[9 + e] = hval * w[e];
    }
#pragma unroll
    for (int j = 0; j < 17; j++) red[j][threadIdx.x] = part[j];
    __syncthreads();
    for (int s = 128; s > 0; s >>= 1) {
        if (threadIdx.x < s)
#pragma unroll
            for (int j = 0; j < 17; j++) red[j][threadIdx.x] += red[j][threadIdx.x + s];
        __syncthreads();
    }
    if (threadIdx.x < 17)
        g_fix_part[(fi * 20 + blockIdx.y) * 17 + threadIdx.x] = red[threadIdx.x][0];
}

__global__ void fixup2_kernel(const float* __restrict__ bi2,
                              const float* __restrict__ br2,
                              const float* __restrict__ bu2) {
    const int fi = blockIdx.x;
    int cnt = g_fix_count; if (cnt > MAXFIX) cnt = MAXFIX;
    if (fi >= cnt) return;
    const int j = threadIdx.x;
    if (j >= 17) return;
    const int t = g_fix_list[fi];
    float s = 0.f;
    for (int p = 0; p < 20; p++) s += g_fix_part[(fi * 20 + p) * 17 + j];
    float bias = (j == 0) ? bi2[0] : (j < 9 ? br2[j - 1] : bu2[j - 9]);
    g_logits[t * 17 + j] = s + bias;
}

// ---------------- router ----------------
__global__ void router_kernel(float* __restrict__ out) {
    const int t = blockIdx.x * blockDim.x + threadIdx.x;
    if (t >= T_TOK) return;
    const float* l = g_logits + t * 17;
    const float l0 = l[0];
    const float imp = 1.f / (1.f + expf(-l0));
    out[IMP_OFF + t] = imp;
    const bool mask = imp > 0.5f;
    float lg[NEXP];
#pragma unroll
    for (int e = 0; e < NEXP; e++) lg[e] = mask ? l[1 + e] : l[9 + e];
    float m = lg[0];
#pragma unroll
    for (int e = 1; e < NEXP; e++) m = fmaxf(m, lg[e]);
    float p[NEXP], s = 0.f;
#pragma unroll
    for (int e = 0; e < NEXP; e++) { p[e] = expf(lg[e] - m); s += p[e]; }
#pragma unroll
    for (int e = 0; e < NEXP; e++) {
        p[e] = p[e] / s;
        out[PROB_OFF + (size_t)t * NEXP + e] = p[e];
    }
    int i0 = 0; float p0 = p[0];
#pragma unroll
    for (int e = 1; e < NEXP; e++) if (p[e] > p0) { p0 = p[e]; i0 = e; }
    int i1 = -1; float p1 = -1.f;
#pragma unroll
    for (int e = 0; e < NEXP; e++) if (e != i0 && p[e] > p1) { p1 = p[e]; i1 = e; }
    const float sn = p0 + p1;
    g_top_i[t] = i0 | (i1 << 8);
    g_top_p[t] = make_float2(p0 / sn, p1 / sn);
    atomicOr(&g_occ0, 1 << i0);
}

// ---------------- scatter ----------------
__global__ void scatter_kernel(float* __restrict__ out) {
    const int t = blockIdx.x * blockDim.x + threadIdx.x;
    if (t >= T_TOK) return;
    const int ii = g_top_i[t];
    const int i0 = ii & 255, i1 = (ii >> 8) & 255;
    const float2 pp = g_top_p[t];
    const int occ = g_occ0;
    size_t b0 = (size_t)(t * NEXP + i0) * CAP;
    out[DISP_OFF + b0] = 1.f;
    out[COMB_OFF + b0] = pp.x;
    const int pos1 = (occ >> i1) & 1;
    size_t b1 = (size_t)(t * NEXP + i1) * CAP + pos1;
    out[DISP_OFF + b1] = 1.f;
    out[COMB_OFF + b1] = pp.y;
}

// ---------------- finalize: aux loss ----------------
__global__ void finalize_kernel(float* __restrict__ out) {
    const int tid = threadIdx.x;
    __shared__ float sr[NEXP][256];
    __shared__ float si[NEXP][256];
    float rl[NEXP], il[NEXP];
#pragma unroll
    for (int e = 0; e < NEXP; e++) { rl[e] = 0.f; il[e] = 0.f; }
    for (int t = tid; t < T_TOK; t += 256) {
        const float l0 = g_logits[t * 17];
        const float mv = (1.f / (1.f + expf(-l0))) > 0.5f ? 1.f : 0.f;
#pragma unroll
        for (int e = 0; e < NEXP; e++) {
            const float pe = out[PROB_OFF + (size_t)t * NEXP + e];
            rl[e] += pe; il[e] += pe * mv;
        }
    }
#pragma unroll
    for (int e = 0; e < NEXP; e++) { sr[e][tid] = rl[e]; si[e][tid] = il[e]; }
    __syncthreads();
    for (int s = 128; s > 0; s >>= 1) {
        if (tid < s)
#pragma unroll
            for (int e = 0; e < NEXP; e++) { sr[e][tid] += sr[e][tid + s]; si[e][tid] += si[e][tid + s]; }
        __syncthreads();
    }
    if (tid == 0) {
        const float EPS = 1e-9f;
        float ent = 0.f, imp_sum[NEXP], tot = 0.f;
#pragma unroll
        for (int e = 0; e < NEXP; e++) {
            const float rppe = sr[e][0] / (float)T_TOK;
            ent += rppe * logf(rppe * (float)NEXP + EPS);
            imp_sum[e] = si[e][0] + EPS; tot += imp_sum[e];
        }
        float ih = 0.f;
#pragma unroll
        for (int e = 0; e < NEXP; e++) {
            const float ipe = imp_sum[e] / tot;
            ih -= ipe * logf(ipe + EPS);
        }
        out[AUX_OFF] = ent - 0.1f * (ih / logf((float)NEXP));
    }
}

// ---------------- launch ----------------
extern "C" void kernel_launch(void* const* d_in, const int* in_sizes, int n_in,
                              void* d_out, int out_size) {
    const float* x   = (const float*)d_in[0];
    const float* Wi1 = (const float*)d_in[1];
    const float* bi1 = (const float*)d_in[2];
    const float* Wi2 = (const float*)d_in[3];
    const float* bi2 = (const float*)d_in[4];
    const float* Wr1 = (const float*)d_in[5];
    const float* br1 = (const float*)d_in[6];
    const float* Wr2 = (const float*)d_in[7];
    const float* br2 = (const float*)d_in[8];
    const float* Wu1 = (const float*)d_in[9];
    const float* bu1 = (const float*)d_in[10];
    const float* Wu2 = (const float*)d_in[11];
    const float* bu2 = (const float*)d_in[12];
    float* out = (float*)d_out;

    cudaFuncSetAttribute(gemm1_mma_kernel, cudaFuncAttributeMaxDynamicSharedMemorySize, SMEM_GEMM);

    zero_kernel<<<2048, 256>>>((float4*)out, (unsigned int)(PROB_OFF / 4));
    split_x_kernel<<<2048, 256>>>((const float4*)x);
    split_w_kernel<<<dim3(NHID / 32, HDIM / 32), dim3(32, 8)>>>(Wi1, Wr1, Wu1);
    gemm1_mma_kernel<<<dim3(NHID / 128, T_TOK / 128), 256, SMEM_GEMM>>>(bi1, br1, bu1);
    gemm2_kernel<<<T_TOK / 8, 256>>>(Wi2, bi2, Wr2, br2, Wu2, bu2);
    flag_kernel<<<T_TOK / 256, 256>>>();
    fixup1_kernel<<<dim3(MAXFIX, 20), 256>>>(x, Wi1, bi1, Wr1, br1, Wu1, bu1, Wi2, Wr2, Wu2);
    fixup2_kernel<<<MAXFIX, 32>>>(bi2, br2, bu2);
    router_kernel<<<T_TOK / 256, 256>>>(out);
    scatter_kernel<<<T_TOK / 256, 256>>>(out);
    finalize_kernel<<<1, 256>>>(out);
}

// round 7
// speedup vs baseline: 1.8065x; 1.1329x over previous
#include <cuda_runtime.h>
#include <cuda_bf16.h>
#include <math.h>
#include <stdint.h>

#define T_TOK 4096
#define HDIM  2048
#define NEXP  8
#define CAP   1536
#define NHID  5120

#define DISP_OFF 0
#define COMB_OFF 50331648
#define PROB_OFF 100663296
#define AUX_OFF  100696064
#define IMP_OFF  100696065

#define TAU 3e-4f
#define MAXFIX 64

// ---------------- device scratch ----------------
__device__ float  g_hidden[(size_t)T_TOK * NHID];
__device__ float  g_logits[T_TOK * 17];
__device__ int    g_top_i[T_TOK];
__device__ float2 g_top_p[T_TOK];
__device__ int    g_occ0;
__device__ __nv_bfloat16 g_Xhi[(size_t)T_TOK * HDIM];
__device__ __nv_bfloat16 g_Xlo[(size_t)T_TOK * HDIM];
__device__ __nv_bfloat16 g_Whi[(size_t)NHID * HDIM];   // [n][k]
__device__ __nv_bfloat16 g_Wlo[(size_t)NHID * HDIM];
__device__ int    g_fix_count;
__device__ int    g_fix_list[MAXFIX];
__device__ float  g_fix_part[MAXFIX * 20 * 17];

// ---------------- helpers ----------------
__device__ __forceinline__ uint32_t smem_u32(const void* p) {
    uint32_t a;
    asm("{ .reg .u64 t; cvta.to.shared.u64 t, %1; cvt.u32.u64 %0, t; }" : "=r"(a) : "l"(p));
    return a;
}
#define SWZ(o) ((o) ^ (((o) >> 3) & 0x70))
#define CP_ASYNC16(dst, src) asm volatile("cp.async.cg.shared.global [%0], [%1], 16;" :: "r"(dst), "l"(src))
#define CP_COMMIT() asm volatile("cp.async.commit_group;" ::: "memory")
#define CP_WAIT(n)  asm volatile("cp.async.wait_group %0;" :: "n"(n) : "memory")

__device__ __forceinline__ void ldsm4(uint32_t& r0, uint32_t& r1, uint32_t& r2, uint32_t& r3, uint32_t addr) {
    asm volatile("ldmatrix.sync.aligned.m8n8.x4.shared.b16 {%0,%1,%2,%3}, [%4];"
        : "=r"(r0), "=r"(r1), "=r"(r2), "=r"(r3) : "r"(addr));
}
__device__ __forceinline__ void mma_bf16(float* d, uint32_t a0, uint32_t a1, uint32_t a2, uint32_t a3,
                                         uint32_t b0, uint32_t b1) {
    asm volatile("mma.sync.aligned.m16n8k16.row.col.f32.bf16.bf16.f32 "
        "{%0,%1,%2,%3}, {%4,%5,%6,%7}, {%8,%9}, {%0,%1,%2,%3};"
        : "+f"(d[0]), "+f"(d[1]), "+f"(d[2]), "+f"(d[3])
        : "r"(a0), "r"(a1), "r"(a2), "r"(a3), "r"(b0), "r"(b1));
}

// ---------------- zero-fill ----------------
__global__ void zero_kernel(float4* __restrict__ out, unsigned int n4) {
    unsigned int i = blockIdx.x * blockDim.x + threadIdx.x;
    unsigned int st = gridDim.x * blockDim.x;
    float4 z = make_float4(0.f, 0.f, 0.f, 0.f);
    for (; i < n4; i += st) out[i] = z;
    if (blockIdx.x == 0 && threadIdx.x == 0) { g_occ0 = 0; g_fix_count = 0; }
}

// ---------------- bf16 hi/lo split ----------------
__device__ __forceinline__ void split1(float x, unsigned short& h, unsigned short& l) {
    __nv_bfloat16 hb = __float2bfloat16_rn(x);
    __nv_bfloat16 lb = __float2bfloat16_rn(x - __bfloat162float(hb));
    h = *(unsigned short*)&hb; l = *(unsigned short*)&lb;
}

__global__ void split_x_kernel(const float4* __restrict__ X) {
    const unsigned int n4 = (unsigned int)((size_t)T_TOK * HDIM / 4);
    unsigned int i = blockIdx.x * blockDim.x + threadIdx.x;
    unsigned int st = gridDim.x * blockDim.x;
    for (; i < n4; i += st) {
        float4 v = X[i];
        ushort4 ph, pl;
        split1(v.x, ph.x, pl.x); split1(v.y, ph.y, pl.y);
        split1(v.z, ph.z, pl.z); split1(v.w, ph.w, pl.w);
        *(ushort4*)(g_Xhi + (size_t)i * 4) = ph;
        *(ushort4*)(g_Xlo + (size_t)i * 4) = pl;
    }
}

__global__ void split_w_kernel(const float* __restrict__ Wi1,
                               const float* __restrict__ Wr1,
                               const float* __restrict__ Wu1) {
    __shared__ float tile[32][33];
    const int tx = threadIdx.x, ty = threadIdx.y;
    const int nb = blockIdx.x * 32, kb = blockIdx.y * 32;
    const float* W; int nl, ld;
    if (nb < 1024)      { W = Wi1; nl = nb;        ld = 1024; }
    else if (nb < 3072) { W = Wr1; nl = nb - 1024; ld = 2048; }
    else                { W = Wu1; nl = nb - 3072; ld = 2048; }
#pragma unroll
    for (int r = 0; r < 4; r++)
        tile[ty + 8 * r][tx] = W[(size_t)(kb + ty + 8 * r) * ld + nl + tx];
    __syncthreads();
#pragma unroll
    for (int r = 0; r < 4; r++) {
        const int n = ty + 8 * r;
        unsigned short h, l;
        split1(tile[tx][n], h, l);
        size_t o = (size_t)(nb + n) * HDIM + kb + tx;
        *(unsigned short*)(g_Whi + o) = h;
        *(unsigned short*)(g_Wlo + o) = l;
    }
}

// ---------------- GEMM1 via mma.sync bf16 (3-product hi/lo) ----------------
#define BKH   64
#define STG   32768
#define NSTG  3
#define SMEM_GEMM (NSTG * STG)
#define KT_TOTAL 96

__device__ __forceinline__ void g1_load_stage(uint32_t sbase, int slot, int kt, int bm, int bn, int tid) {
    const int sec = kt >> 5;
    const int k0 = (kt & 31) * BKH;
    const __nv_bfloat16* Ap = (sec == 2) ? g_Xlo : g_Xhi;
    const __nv_bfloat16* Bp = (sec == 1) ? g_Wlo : g_Whi;
    uint32_t sA = sbase + slot * STG;
    uint32_t sB = sA + 16384;
#pragma unroll
    for (int it = 0; it < 4; it++) {
        int seg = it * 256 + tid;
        int row = seg >> 3, ks = seg & 7;
        CP_ASYNC16(sA + SWZ(row * 128 + ks * 16),
                   Ap + (size_t)(bm * 128 + row) * HDIM + k0 + ks * 8);
    }
#pragma unroll
    for (int it = 0; it < 4; it++) {
        int seg = it * 256 + tid;
        int row = seg >> 3, ks = seg & 7;
        CP_ASYNC16(sB + SWZ(row * 128 + ks * 16),
                   Bp + (size_t)(bn * 128 + row) * HDIM + k0 + ks * 8);
    }
    CP_COMMIT();
}

__global__ __launch_bounds__(256, 2)
void gemm1_mma_kernel(const float* __restrict__ bi1,
                      const float* __restrict__ br1,
                      const float* __restrict__ bu1) {
    extern __shared__ char smem[];
    __shared__ float bias_s[128];
    const uint32_t sbase = smem_u32(smem);
    const int tid = threadIdx.x, wid = tid >> 5, lane = tid & 31;
    const int wm = wid & 3, wn = wid >> 2;
    const int bn = blockIdx.x, bm = blockIdx.y;
    const int n0 = bn * 128;

    if (tid < 128) {
        const float* bias; int nl;
        if (n0 < 1024)      { bias = bi1; nl = n0; }
        else if (n0 < 3072) { bias = br1; nl = n0 - 1024; }
        else                { bias = bu1; nl = n0 - 3072; }
        bias_s[tid] = bias[nl + tid];
    }

    float d[2][8][4];
#pragma unroll
    for (int i = 0; i < 2; i++)
#pragma unroll
        for (int j = 0; j < 8; j++)
#pragma unroll
            for (int c = 0; c < 4; c++) d[i][j][c] = 0.f;

    g1_load_stage(sbase, 0, 0, bm, bn, tid);
    g1_load_stage(sbase, 1, 1, bm, bn, tid);

    const int lrow = lane & 15;
    const int lcol16 = (lane >> 4) * 16;

    for (int kt = 0; kt < KT_TOTAL; kt++) {
        if (kt + 2 < KT_TOTAL) { CP_WAIT(1); } else { CP_WAIT(0); }
        __syncthreads();                                   // single sync per chunk
        if (kt + 2 < KT_TOTAL) g1_load_stage(sbase, (kt + 2) % NSTG, kt + 2, bm, bn, tid);

        const int slot = kt % NSTG;
        const uint32_t sA = sbase + slot * STG;
        const uint32_t sB = sA + 16384;
#pragma unroll
        for (int ks = 0; ks < 4; ks++) {
            uint32_t a[2][4];
#pragma unroll
            for (int im = 0; im < 2; im++) {
                int row = wm * 32 + im * 16 + lrow;
                ldsm4(a[im][0], a[im][1], a[im][2], a[im][3],
                      sA + SWZ(row * 128 + ks * 32 + lcol16));
            }
            uint32_t bfr[8][2];
#pragma unroll
            for (int ib = 0; ib < 4; ib++) {
                int row = wn * 64 + ib * 16 + lrow;
                uint32_t r0, r1, r2, r3;
                ldsm4(r0, r1, r2, r3, sB + SWZ(row * 128 + ks * 32 + lcol16));
                bfr[2 * ib][0] = r0;     bfr[2 * ib][1] = r2;
                bfr[2 * ib + 1][0] = r1; bfr[2 * ib + 1][1] = r3;
            }
#pragma unroll
            for (int im = 0; im < 2; im++)
#pragma unroll
                for (int jn = 0; jn < 8; jn++)
                    mma_bf16(d[im][jn], a[im][0], a[im][1], a[im][2], a[im][3],
                             bfr[jn][0], bfr[jn][1]);
        }
    }

    // epilogue: bias + relu -> g_hidden
    const int r0 = lane >> 2;
    const int c0 = (lane & 3) * 2;
#pragma unroll
    for (int im = 0; im < 2; im++) {
        const int mg = bm * 128 + wm * 32 + im * 16;
#pragma unroll
        for (int jn = 0; jn < 8; jn++) {
            const int nl = wn * 64 + jn * 8 + c0;
            const float b0 = bias_s[nl], b1 = bias_s[nl + 1];
            float2 v0 = make_float2(fmaxf(d[im][jn][0] + b0, 0.f), fmaxf(d[im][jn][1] + b1, 0.f));
            float2 v1 = make_float2(fmaxf(d[im][jn][2] + b0, 0.f), fmaxf(d[im][jn][3] + b1, 0.f));
            *(float2*)(g_hidden + (size_t)(mg + r0) * NHID + n0 + nl) = v0;
            *(float2*)(g_hidden + (size_t)(mg + r0 + 8) * NHID + n0 + nl) = v1;
        }
    }
}

// ---------------- GEMM2: warp per token ----------------
__global__ void gemm2_kernel(const float* __restrict__ Wi2, const float* __restrict__ bi2,
                             const float* __restrict__ Wr2, const float* __restrict__ br2,
                             const float* __restrict__ Wu2, const float* __restrict__ bu2) {
    const int gw = (blockIdx.x * blockDim.x + threadIdx.x) >> 5;
    const int lane = threadIdx.x & 31;
    if (gw >= T_TOK) return;
    const float* h = g_hidden + (size_t)gw * NHID;
    float acc[17];
#pragma unroll
    for (int j = 0; j < 17; j++) acc[j] = 0.f;
#pragma unroll
    for (int it = 0; it < 8; it++) {
        const int k = it * 128 + lane * 4;
        float4 hv = *(const float4*)(h + k);
        float4 wv = *(const float4*)(Wi2 + k);
        acc[0] += hv.x * wv.x + hv.y * wv.y + hv.z * wv.z + hv.w * wv.w;
    }
#pragma unroll 4
    for (int it = 0; it < 16; it++) {
        const int k = it * 128 + lane * 4;
        float4 hv = *(const float4*)(h + 1024 + k);
        const float* wr = Wr2 + (size_t)k * 8;
        float hq[4] = {hv.x, hv.y, hv.z, hv.w};
#pragma unroll
        for (int q = 0; q < 4; q++) {
            float4 w0 = *(const float4*)(wr + q * 8);
            float4 w1 = *(const float4*)(wr + q * 8 + 4);
            acc[1] += hq[q] * w0.x; acc[2] += hq[q] * w0.y; acc[3] += hq[q] * w0.z; acc[4] += hq[q] * w0.w;
            acc[5] += hq[q] * w1.x; acc[6] += hq[q] * w1.y; acc[7] += hq[q] * w1.z; acc[8] += hq[q] * w1.w;
        }
    }
#pragma unroll 4
    for (int it = 0; it < 16; it++) {
        const int k = it * 128 + lane * 4;
        float4 hv = *(const float4*)(h + 3072 + k);
        const float* wu = Wu2 + (size_t)k * 8;
        float hq[4] = {hv.x, hv.y, hv.z, hv.w};
#pragma unroll
        for (int q = 0; q < 4; q++) {
            float4 w0 = *(const float4*)(wu + q * 8);
            float4 w1 = *(const float4*)(wu + q * 8 + 4);
            acc[9]  += hq[q] * w0.x; acc[10] += hq[q] * w0.y; acc[11] += hq[q] * w0.z; acc[12] += hq[q] * w0.w;
            acc[13] += hq[q] * w1.x; acc[14] += hq[q] * w1.y; acc[15] += hq[q] * w1.z; acc[16] += hq[q] * w1.w;
        }
    }
#pragma unroll
    for (int j = 0; j < 17; j++)
#pragma unroll
        for (int off = 16; off > 0; off >>= 1)
            acc[j] += __shfl_xor_sync(0xffffffffu, acc[j], off);
    if (lane == 0) {
        float* o = g_logits + gw * 17;
        o[0] = acc[0] + bi2[0];
#pragma unroll
        for (int e = 0; e < NEXP; e++) o[1 + e] = acc[1 + e] + br2[e];
#pragma unroll
        for (int e = 0; e < NEXP; e++) o[9 + e] = acc[9 + e] + bu2[e];
    }
}

// ---------------- flag borderline tokens ----------------
__global__ void flag_kernel() {
    const int t = blockIdx.x * blockDim.x + threadIdx.x;
    if (t >= T_TOK) return;
    const float* l = g_logits + t * 17;
    const float l0 = l[0];
    bool flag = fabsf(l0) < TAU;
    const bool mask = l0 > 0.f;
    float lg[NEXP];
#pragma unroll
    for (int e = 0; e < NEXP; e++) lg[e] = mask ? l[1 + e] : l[9 + e];
    float v1 = -1e30f, v2 = -1e30f, v3 = -1e30f;
#pragma unroll
    for (int e = 0; e < NEXP; e++) {
        float v = lg[e];
        if (v > v1)      { v3 = v2; v2 = v1; v1 = v; }
        else if (v > v2) { v3 = v2; v2 = v; }
        else if (v > v3) { v3 = v; }
    }
    if (v1 - v2 < TAU || v2 - v3 < TAU) flag = true;
    if (flag) {
        int idx = atomicAdd(&g_fix_count, 1);
        if (idx < MAXFIX) g_fix_list[idx] = t;
    }
}

// ---------------- exact fp32 recompute for flagged tokens ----------------
__global__ void fixup1_kernel(const float* __restrict__ X,
                              const float* __restrict__ Wi1, const float* __restrict__ bi1,
                              const float* __restrict__ Wr1, const float* __restrict__ br1,
                              const float* __restrict__ Wu1, const float* __restrict__ bu1,
                              const float* __restrict__ Wi2,
                              const float* __restrict__ Wr2,
                              const float* __restrict__ Wu2) {
    const int fi = blockIdx.x;
    int cnt = g_fix_count; if (cnt > MAXFIX) cnt = MAXFIX;
    if (fi >= cnt) return;
    const int t = g_fix_list[fi];
    const int n = blockIdx.y * 256 + threadIdx.x;
    __shared__ float xs[HDIM];
    __shared__ float red[17][257];
    for (int k = threadIdx.x; k < HDIM; k += 256) xs[k] = X[(size_t)t * HDIM + k];
    __syncthreads();

    const float* W; const float* b; int nl, ld;
    if (n < 1024)      { W = Wi1; b = bi1; nl = n;        ld = 1024; }
    else if (n < 3072) { W = Wr1; b = br1; nl = n - 1024; ld = 2048; }
    else               { W = Wu1; b = bu1; nl = n - 3072; ld = 2048; }
    float acc = 0.f;
    for (int k = 0; k < HDIM; k++) acc = fmaf(xs[k], W[(size_t)k * ld + nl], acc);
    float hval = fmaxf(acc + b[nl], 0.f);

    float part[17];
#pragma unroll
    for (int j = 0; j < 17; j++) part[j] = 0.f;
    if (n < 1024) part[0] = hval * Wi2[n];
    else if (n < 3072) {
        const float* w = Wr2 + (size_t)(n - 1024) * 8;
#pragma unroll
        for (int e = 0; e < NEXP; e++) part[1 + e] = hval * w[e];
    } else {
        const float* w = Wu2 + (size_t)(n - 3072) * 8;
#pragma unroll
        for (int e = 0; e < NEXP; e++) part[9 + e] = hval * w[e];
    }
#pragma unroll
    for (int j = 0; j < 17; j++) red[j][threadIdx.x] = part[j];
    __syncthreads();
    for (int s = 128; s > 0; s >>= 1) {
        if (threadIdx.x < s)
#pragma unroll
            for (int j = 0; j < 17; j++) red[j][threadIdx.x] += red[j][threadIdx.x + s];
        __syncthreads();
    }
    if (threadIdx.x < 17)
        g_fix_part[(fi * 20 + blockIdx.y) * 17 + threadIdx.x] = red[threadIdx.x][0];
}

__global__ void fixup2_kernel(const float* __restrict__ bi2,
                              const float* __restrict__ br2,
                              const float* __restrict__ bu2) {
    const int fi = blockIdx.x;
    int cnt = g_fix_count; if (cnt > MAXFIX) cnt = MAXFIX;
    if (fi >= cnt) return;
    const int j = threadIdx.x;
    if (j >= 17) return;
    const int t = g_fix_list[fi];
    float s = 0.f;
    for (int p = 0; p < 20; p++) s += g_fix_part[(fi * 20 + p) * 17 + j];
    float bias = (j == 0) ? bi2[0] : (j < 9 ? br2[j - 1] : bu2[j - 9]);
    g_logits[t * 17 + j] = s + bias;
}

// ---------------- router ----------------
__global__ void router_kernel(float* __restrict__ out) {
    const int t = blockIdx.x * blockDim.x + threadIdx.x;
    if (t >= T_TOK) return;
    const float* l = g_logits + t * 17;
    const float l0 = l[0];
    const float imp = 1.f / (1.f + expf(-l0));
    out[IMP_OFF + t] = imp;
    const bool mask = imp > 0.5f;
    float lg[NEXP];
#pragma unroll
    for (int e = 0; e < NEXP; e++) lg[e] = mask ? l[1 + e] : l[9 + e];
    float m = lg[0];
#pragma unroll
    for (int e = 1; e < NEXP; e++) m = fmaxf(m, lg[e]);
    float p[NEXP], s = 0.f;
#pragma unroll
    for (int e = 0; e < NEXP; e++) { p[e] = expf(lg[e] - m); s += p[e]; }
#pragma unroll
    for (int e = 0; e < NEXP; e++) {
        p[e] = p[e] / s;
        out[PROB_OFF + (size_t)t * NEXP + e] = p[e];
    }
    int i0 = 0; float p0 = p[0];
#pragma unroll
    for (int e = 1; e < NEXP; e++) if (p[e] > p0) { p0 = p[e]; i0 = e; }
    int i1 = -1; float p1 = -1.f;
#pragma unroll
    for (int e = 0; e < NEXP; e++) if (e != i0 && p[e] > p1) { p1 = p[e]; i1 = e; }
    const float sn = p0 + p1;
    g_top_i[t] = i0 | (i1 << 8);
    g_top_p[t] = make_float2(p0 / sn, p1 / sn);
    atomicOr(&g_occ0, 1 << i0);
}

// ---------------- scatter ----------------
__global__ void scatter_kernel(float* __restrict__ out) {
    const int t = blockIdx.x * blockDim.x + threadIdx.x;
    if (t >= T_TOK) return;
    const int ii = g_top_i[t];
    const int i0 = ii & 255, i1 = (ii >> 8) & 255;
    const float2 pp = g_top_p[t];
    const int occ = g_occ0;
    size_t b0 = (size_t)(t * NEXP + i0) * CAP;
    out[DISP_OFF + b0] = 1.f;
    out[COMB_OFF + b0] = pp.x;
    const int pos1 = (occ >> i1) & 1;
    size_t b1 = (size_t)(t * NEXP + i1) * CAP + pos1;
    out[DISP_OFF + b1] = 1.f;
    out[COMB_OFF + b1] = pp.y;
}

// ---------------- finalize: aux loss ----------------
__global__ void finalize_kernel(float* __restrict__ out) {
    const int tid = threadIdx.x;
    __shared__ float sr[NEXP][256];
    __shared__ float si[NEXP][256];
    float rl[NEXP], il[NEXP];
#pragma unroll
    for (int e = 0; e < NEXP; e++) { rl[e] = 0.f; il[e] = 0.f; }
    for (int t = tid; t < T_TOK; t += 256) {
        const float l0 = g_logits[t * 17];
        const float mv = (1.f / (1.f + expf(-l0))) > 0.5f ? 1.f : 0.f;
#pragma unroll
        for (int e = 0; e < NEXP; e++) {
            const float pe = out[PROB_OFF + (size_t)t * NEXP + e];
            rl[e] += pe; il[e] += pe * mv;
        }
    }
#pragma unroll
    for (int e = 0; e < NEXP; e++) { sr[e][tid] = rl[e]; si[e][tid] = il[e]; }
    __syncthreads();
    for (int s = 128; s > 0; s >>= 1) {
        if (tid < s)
#pragma unroll
            for (int e = 0; e < NEXP; e++) { sr[e][tid] += sr[e][tid + s]; si[e][tid] += si[e][tid + s]; }
        __syncthreads();
    }
    if (tid == 0) {
        const float EPS = 1e-9f;
        float ent = 0.f, imp_sum[NEXP], tot = 0.f;
#pragma unroll
        for (int e = 0; e < NEXP; e++) {
            const float rppe = sr[e][0] / (float)T_TOK;
            ent += rppe * logf(rppe * (float)NEXP + EPS);
            imp_sum[e] = si[e][0] + EPS; tot += imp_sum[e];
        }
        float ih = 0.f;
#pragma unroll
        for (int e = 0; e < NEXP; e++) {
            const float ipe = imp_sum[e] / tot;
            ih -= ipe * logf(ipe + EPS);
        }
        out[AUX_OFF] = ent - 0.1f * (ih / logf((float)NEXP));
    }
}

// ---------------- launch ----------------
extern "C" void kernel_launch(void* const* d_in, const int* in_sizes, int n_in,
                              void* d_out, int out_size) {
    const float* x   = (const float*)d_in[0];
    const float* Wi1 = (const float*)d_in[1];
    const float* bi1 = (const float*)d_in[2];
    const float* Wi2 = (const float*)d_in[3];
    const float* bi2 = (const float*)d_in[4];
    const float* Wr1 = (const float*)d_in[5];
    const float* br1 = (const float*)d_in[6];
    const float* Wr2 = (const float*)d_in[7];
    const float* br2 = (const float*)d_in[8];
    const float* Wu1 = (const float*)d_in[9];
    const float* bu1 = (const float*)d_in[10];
    const float* Wu2 = (const float*)d_in[11];
    const float* bu2 = (const float*)d_in[12];
    float* out = (float*)d_out;

    cudaFuncSetAttribute(gemm1_mma_kernel, cudaFuncAttributeMaxDynamicSharedMemorySize, SMEM_GEMM);

    zero_kernel<<<2048, 256>>>((float4*)out, (unsigned int)(PROB_OFF / 4));
    split_x_kernel<<<2048, 256>>>((const float4*)x);
    split_w_kernel<<<dim3(NHID / 32, HDIM / 32), dim3(32, 8)>>>(Wi1, Wr1, Wu1);
    gemm1_mma_kernel<<<dim3(NHID / 128, T_TOK / 128), 256, SMEM_GEMM>>>(bi1, br1, bu1);
    gemm2_kernel<<<T_TOK / 8, 256>>>(Wi2, bi2, Wr2, br2, Wu2, bu2);
    flag_kernel<<<T_TOK / 256, 256>>>();
    fixup1_kernel<<<dim3(MAXFIX, 20), 256>>>(x, Wi1, bi1, Wr1, br1, Wu1, bu1, Wi2, Wr2, Wu2);
    fixup2_kernel<<<MAXFIX, 32>>>(bi2, br2, bu2);
    router_kernel<<<T_TOK / 256, 256>>>(out);
    scatter_kernel<<<T_TOK / 256, 256>>>(out);
    finalize_kernel<<<1, 256>>>(out);
}

// round 9
// speedup vs baseline: 1.9940x; 1.1038x over previous
#include <cuda_runtime.h>
#include <cuda_bf16.h>
#include <math.h>
#include <stdint.h>

#define T_TOK 4096
#define HDIM  2048
#define NEXP  8
#define CAP   1536
#define NHID  5120

#define DISP_OFF 0
#define COMB_OFF 50331648
#define PROB_OFF 100663296
#define AUX_OFF  100696064
#define IMP_OFF  100696065

#define TAU 3e-4f
#define MAXFIX 64

// ---------------- device scratch ----------------
__device__ float  g_logits[T_TOK * 17];
__device__ int    g_top_i[T_TOK];
__device__ float2 g_top_p[T_TOK];
__device__ int    g_occ0;
__device__ __nv_bfloat16 g_Xhi[(size_t)T_TOK * HDIM];
__device__ __nv_bfloat16 g_Xlo[(size_t)T_TOK * HDIM];
__device__ __nv_bfloat16 g_Whi[(size_t)NHID * HDIM];   // [n][k]
__device__ __nv_bfloat16 g_Wlo[(size_t)NHID * HDIM];
__device__ int    g_fix_count;
__device__ int    g_fix_list[MAXFIX];
__device__ float  g_fix_part[MAXFIX * 20 * 17];

// ---------------- helpers ----------------
__device__ __forceinline__ uint32_t smem_u32(const void* p) {
    uint32_t a;
    asm("{ .reg .u64 t; cvta.to.shared.u64 t, %1; cvt.u32.u64 %0, t; }" : "=r"(a) : "l"(p));
    return a;
}
#define SWZ(o) ((o) ^ (((o) >> 3) & 0x70))
#define CP_ASYNC16(dst, src) asm volatile("cp.async.cg.shared.global [%0], [%1], 16;" :: "r"(dst), "l"(src))
#define CP_COMMIT() asm volatile("cp.async.commit_group;" ::: "memory")
#define CP_WAIT(n)  asm volatile("cp.async.wait_group %0;" :: "n"(n) : "memory")

__device__ __forceinline__ void ldsm4(uint32_t& r0, uint32_t& r1, uint32_t& r2, uint32_t& r3, uint32_t addr) {
    asm volatile("ldmatrix.sync.aligned.m8n8.x4.shared.b16 {%0,%1,%2,%3}, [%4];"
        : "=r"(r0), "=r"(r1), "=r"(r2), "=r"(r3) : "r"(addr));
}
__device__ __forceinline__ void mma_bf16(float* d, uint32_t a0, uint32_t a1, uint32_t a2, uint32_t a3,
                                         uint32_t b0, uint32_t b1) {
    asm volatile("mma.sync.aligned.m16n8k16.row.col.f32.bf16.bf16.f32 "
        "{%0,%1,%2,%3}, {%4,%5,%6,%7}, {%8,%9}, {%0,%1,%2,%3};"
        : "+f"(d[0]), "+f"(d[1]), "+f"(d[2]), "+f"(d[3])
        : "r"(a0), "r"(a1), "r"(a2), "r"(a3), "r"(b0), "r"(b1));
}

// ---------------- zero-fill ----------------
__global__ void zero_kernel(float4* __restrict__ out, unsigned int n4) {
    unsigned int i = blockIdx.x * blockDim.x + threadIdx.x;
    unsigned int st = gridDim.x * blockDim.x;
    float4 z = make_float4(0.f, 0.f, 0.f, 0.f);
    for (; i < n4; i += st) out[i] = z;
    if (blockIdx.x == 0 && threadIdx.x == 0) { g_occ0 = 0; g_fix_count = 0; }
}

// ---------------- bf16 hi/lo split ----------------
__device__ __forceinline__ void split1(float x, unsigned short& h, unsigned short& l) {
    __nv_bfloat16 hb = __float2bfloat16_rn(x);
    __nv_bfloat16 lb = __float2bfloat16_rn(x - __bfloat162float(hb));
    h = *(unsigned short*)&hb; l = *(unsigned short*)&lb;
}

__global__ void split_x_kernel(const float4* __restrict__ X) {
    const unsigned int n4 = (unsigned int)((size_t)T_TOK * HDIM / 4);
    unsigned int i = blockIdx.x * blockDim.x + threadIdx.x;
    unsigned int st = gridDim.x * blockDim.x;
    for (; i < n4; i += st) {
        float4 v = X[i];
        ushort4 ph, pl;
        split1(v.x, ph.x, pl.x); split1(v.y, ph.y, pl.y);
        split1(v.z, ph.z, pl.z); split1(v.w, ph.w, pl.w);
        *(ushort4*)(g_Xhi + (size_t)i * 4) = ph;
        *(ushort4*)(g_Xlo + (size_t)i * 4) = pl;
    }
}

__global__ void split_w_kernel(const float* __restrict__ Wi1,
                               const float* __restrict__ Wr1,
                               const float* __restrict__ Wu1) {
    __shared__ float tile[32][33];
    const int tx = threadIdx.x, ty = threadIdx.y;
    const int nb = blockIdx.x * 32, kb = blockIdx.y * 32;
    const float* W; int nl, ld;
    if (nb < 1024)      { W = Wi1; nl = nb;        ld = 1024; }
    else if (nb < 3072) { W = Wr1; nl = nb - 1024; ld = 2048; }
    else                { W = Wu1; nl = nb - 3072; ld = 2048; }
#pragma unroll
    for (int r = 0; r < 4; r++)
        tile[ty + 8 * r][tx] = W[(size_t)(kb + ty + 8 * r) * ld + nl + tx];
    __syncthreads();
#pragma unroll
    for (int r = 0; r < 4; r++) {
        const int n = ty + 8 * r;
        unsigned short h, l;
        split1(tile[tx][n], h, l);
        size_t o = (size_t)(nb + n) * HDIM + kb + tx;
        *(unsigned short*)(g_Whi + o) = h;
        *(unsigned short*)(g_Wlo + o) = l;
    }
}

// ---------------- init logits with biases (atomic partials add onto these) ----------------
__global__ void init_logits_kernel(const float* __restrict__ bi2,
                                   const float* __restrict__ br2,
                                   const float* __restrict__ bu2) {
    const int t = blockIdx.x * blockDim.x + threadIdx.x;
    if (t >= T_TOK) return;
    float* o = g_logits + t * 17;
    o[0] = bi2[0];
#pragma unroll
    for (int e = 0; e < NEXP; e++) o[1 + e] = br2[e];
#pragma unroll
    for (int e = 0; e < NEXP; e++) o[9 + e] = bu2[e];
}

// ---------------- GEMM1 via mma.sync bf16 (3-product hi/lo) + fused layer-2 epilogue ----------------
#define BKH   64
#define STG   32768
#define NSTG  3
#define SMEM_GEMM (NSTG * STG)
#define KT_TOTAL 96
#define TPAD 132           // tile row stride (floats)

__device__ __forceinline__ void g1_load_stage(uint32_t sbase, int slot, int kt, int bm, int bn, int tid) {
    const int sec = kt >> 5;
    const int k0 = (kt & 31) * BKH;
    const __nv_bfloat16* Ap = (sec == 2) ? g_Xlo : g_Xhi;
    const __nv_bfloat16* Bp = (sec == 1) ? g_Wlo : g_Whi;
    uint32_t sA = sbase + slot * STG;
    uint32_t sB = sA + 16384;
#pragma unroll
    for (int it = 0; it < 4; it++) {
        int seg = it * 256 + tid;
        int row = seg >> 3, ks = seg & 7;
        CP_ASYNC16(sA + SWZ(row * 128 + ks * 16),
                   Ap + (size_t)(bm * 128 + row) * HDIM + k0 + ks * 8);
    }
#pragma unroll
    for (int it = 0; it < 4; it++) {
        int seg = it * 256 + tid;
        int row = seg >> 3, ks = seg & 7;
        CP_ASYNC16(sB + SWZ(row * 128 + ks * 16),
                   Bp + (size_t)(bn * 128 + row) * HDIM + k0 + ks * 8);
    }
    CP_COMMIT();
}

__global__ __launch_bounds__(256, 2)
void gemm1_mma_kernel(const float* __restrict__ bi1,
                      const float* __restrict__ br1,
                      const float* __restrict__ bu1,
                      const float* __restrict__ Wi2,
                      const float* __restrict__ Wr2,
                      const float* __restrict__ Wu2) {
    extern __shared__ char smem[];
    __shared__ float bias_s[128];
    const uint32_t sbase = smem_u32(smem);
    const int tid = threadIdx.x, wid = tid >> 5, lane = tid & 31;
    const int wm = wid & 3, wn = wid >> 2;
    const int bn = blockIdx.x, bm = blockIdx.y;
    const int n0 = bn * 128;

    int hsel, nl0;
    if (n0 < 1024)      { hsel = 0; nl0 = n0; }
    else if (n0 < 3072) { hsel = 1; nl0 = n0 - 1024; }
    else                { hsel = 2; nl0 = n0 - 3072; }

    if (tid < 128) {
        const float* bias = (hsel == 0) ? bi1 : (hsel == 1 ? br1 : bu1);
        bias_s[tid] = bias[nl0 + tid];
    }

    float d[2][8][4];
#pragma unroll
    for (int i = 0; i < 2; i++)
#pragma unroll
        for (int j = 0; j < 8; j++)
#pragma unroll
            for (int c = 0; c < 4; c++) d[i][j][c] = 0.f;

    g1_load_stage(sbase, 0, 0, bm, bn, tid);
    g1_load_stage(sbase, 1, 1, bm, bn, tid);

    const int lrow = lane & 15;
    const int lcol16 = (lane >> 4) * 16;

    for (int kt = 0; kt < KT_TOTAL; kt++) {
        if (kt + 2 < KT_TOTAL) { CP_WAIT(1); } else { CP_WAIT(0); }
        __syncthreads();
        if (kt + 2 < KT_TOTAL) g1_load_stage(sbase, (kt + 2) % NSTG, kt + 2, bm, bn, tid);

        const int slot = kt % NSTG;
        const uint32_t sA = sbase + slot * STG;
        const uint32_t sB = sA + 16384;
#pragma unroll
        for (int ks = 0; ks < 4; ks++) {
            uint32_t a[2][4];
#pragma unroll
            for (int im = 0; im < 2; im++) {
                int row = wm * 32 + im * 16 + lrow;
                ldsm4(a[im][0], a[im][1], a[im][2], a[im][3],
                      sA + SWZ(row * 128 + ks * 32 + lcol16));
            }
            uint32_t bfr[8][2];
#pragma unroll
            for (int ib = 0; ib < 4; ib++) {
                int row = wn * 64 + ib * 16 + lrow;
                uint32_t r0, r1, r2, r3;
                ldsm4(r0, r1, r2, r3, sB + SWZ(row * 128 + ks * 32 + lcol16));
                bfr[2 * ib][0] = r0;     bfr[2 * ib][1] = r2;
                bfr[2 * ib + 1][0] = r1; bfr[2 * ib + 1][1] = r3;
            }
#pragma unroll
            for (int im = 0; im < 2; im++)
#pragma unroll
                for (int jn = 0; jn < 8; jn++)
                    mma_bf16(d[im][jn], a[im][0], a[im][1], a[im][2], a[im][3],
                             bfr[jn][0], bfr[jn][1]);
        }
    }

    // ---- fused epilogue: relu tile -> smem, then layer-2 partials -> atomicAdd g_logits ----
    __syncthreads();   // all warps done reading stage smem
    float* tile = (float*)smem;   // 128 x TPAD floats (67.6 KB <= 96 KB)
    const int r0 = lane >> 2;
    const int c0 = (lane & 3) * 2;
#pragma unroll
    for (int im = 0; im < 2; im++) {
        const int ml = wm * 32 + im * 16 + r0;
#pragma unroll
        for (int jn = 0; jn < 8; jn++) {
            const int nl = wn * 64 + jn * 8 + c0;
            const float b0 = bias_s[nl], b1 = bias_s[nl + 1];
            tile[ml * TPAD + nl]           = fmaxf(d[im][jn][0] + b0, 0.f);
            tile[ml * TPAD + nl + 1]       = fmaxf(d[im][jn][1] + b1, 0.f);
            tile[(ml + 8) * TPAD + nl]     = fmaxf(d[im][jn][2] + b0, 0.f);
            tile[(ml + 8) * TPAD + nl + 1] = fmaxf(d[im][jn][3] + b1, 0.f);
        }
    }
    __syncthreads();

    if (hsel == 0) {
        const float w0 = Wi2[nl0 + lane], w1 = Wi2[nl0 + lane + 32];
        const float w2 = Wi2[nl0 + lane + 64], w3 = Wi2[nl0 + lane + 96];
        for (int r = 0; r < 16; r++) {
            const int m = wid * 16 + r;
            const float* tr = tile + m * TPAD;
            float p = tr[lane] * w0 + tr[lane + 32] * w1 + tr[lane + 64] * w2 + tr[lane + 96] * w3;
#pragma unroll
            for (int off = 16; off > 0; off >>= 1) p += __shfl_xor_sync(0xffffffffu, p, off);
            if (lane == 0) atomicAdd(&g_logits[(size_t)(bm * 128 + m) * 17], p);
        }
    } else {
        const float* W2 = (hsel == 1) ? Wr2 : Wu2;
        const int jb = (hsel == 1) ? 1 : 9;
        float w[4][8];
#pragma unroll
        for (int q = 0; q < 4; q++) {
            const float* wp = W2 + (size_t)(nl0 + lane + 32 * q) * 8;
            float4 a4 = *(const float4*)wp;
            float4 b4 = *(const float4*)(wp + 4);
            w[q][0] = a4.x; w[q][1] = a4.y; w[q][2] = a4.z; w[q][3] = a4.w;
            w[q][4] = b4.x; w[q][5] = b4.y; w[q][6] = b4.z; w[q][7] = b4.w;
        }
        for (int r = 0; r < 16; r++) {
            const int m = wid * 16 + r;
            const float* tr = tile + m * TPAD;
            const float v0 = tr[lane], v1 = tr[lane + 32], v2 = tr[lane + 64], v3 = tr[lane + 96];
            float p[8];
#pragma unroll
            for (int e = 0; e < 8; e++)
                p[e] = v0 * w[0][e] + v1 * w[1][e] + v2 * w[2][e] + v3 * w[3][e];
#pragma unroll
            for (int e = 0; e < 8; e++)
#pragma unroll
                for (int off = 16; off > 0; off >>= 1)
                    p[e] += __shfl_xor_sync(0xffffffffu, p[e], off);
            if (lane == 0) {
                float* gl = g_logits + (size_t)(bm * 128 + m) * 17 + jb;
#pragma unroll
                for (int e = 0; e < 8; e++) atomicAdd(gl + e, p[e]);
            }
        }
    }
}

// ---------------- flag borderline tokens ----------------
__global__ void flag_kernel() {
    const int t = blockIdx.x * blockDim.x + threadIdx.x;
    if (t >= T_TOK) return;
    const float* l = g_logits + t * 17;
    const float l0 = l[0];
    bool flag = fabsf(l0) < TAU;
    const bool mask = l0 > 0.f;
    float lg[NEXP];
#pragma unroll
    for (int e = 0; e < NEXP; e++) lg[e] = mask ? l[1 + e] : l[9 + e];
    float v1 = -1e30f, v2 = -1e30f, v3 = -1e30f;
#pragma unroll
    for (int e = 0; e < NEXP; e++) {
        float v = lg[e];
        if (v > v1)      { v3 = v2; v2 = v1; v1 = v; }
        else if (v > v2) { v3 = v2; v2 = v; }
        else if (v > v3) { v3 = v; }
    }
    if (v1 - v2 < TAU || v2 - v3 < TAU) flag = true;
    if (flag) {
        int idx = atomicAdd(&g_fix_count, 1);
        if (idx < MAXFIX) g_fix_list[idx] = t;
    }
}

// ---------------- exact fp32 recompute for flagged tokens ----------------
__global__ void fixup1_kernel(const float* __restrict__ X,
                              const float* __restrict__ Wi1, const float* __restrict__ bi1,
                              const float* __restrict__ Wr1, const float* __restrict__ br1,
                              const float* __restrict__ Wu1, const float* __restrict__ bu1,
                              const float* __restrict__ Wi2,
                              const float* __restrict__ Wr2,
                              const float* __restrict__ Wu2) {
    const int fi = blockIdx.x;
    int cnt = g_fix_count; if (cnt > MAXFIX) cnt = MAXFIX;
    if (fi >= cnt) return;
    const int t = g_fix_list[fi];
    const int n = blockIdx.y * 256 + threadIdx.x;
    __shared__ float xs[HDIM];
    __shared__ float red[17][257];
    for (int k = threadIdx.x; k < HDIM; k += 256) xs[k] = X[(size_t)t * HDIM + k];
    __syncthreads();

    const float* W; const float* b; int nl, ld;
    if (n < 1024)      { W = Wi1; b = bi1; nl = n;        ld = 1024; }
    else if (n < 3072) { W = Wr1; b = br1; nl = n - 1024; ld = 2048; }
    else               { W = Wu1; b = bu1; nl = n - 3072; ld = 2048; }
    float acc = 0.f;
    for (int k = 0; k < HDIM; k++) acc = fmaf(xs[k], W[(size_t)k * ld + nl], acc);
    float hval = fmaxf(acc + b[nl], 0.f);

    float part[17];
#pragma unroll
    for (int j = 0; j < 17; j++) part[j] = 0.f;
    if (n < 1024) part[0] = hval * Wi2[n];
    else if (n < 3072) {
        const float* w = Wr2 + (size_t)(n - 1024) * 8;
#pragma unroll
        for (int e = 0; e < NEXP; e++) part[1 + e] = hval * w[e];
    } else {
        const float* w = Wu2 + (size_t)(n - 3072) * 8;
#pragma unroll
        for (int e = 0; e < NEXP; e++) part[9 + e] = hval * w[e];
    }
#pragma unroll
    for (int j = 0; j < 17; j++) red[j][threadIdx.x] = part[j];
    __syncthreads();
    for (int s = 128; s > 0; s >>= 1) {
        if (threadIdx.x < s)
#pragma unroll
            for (int j = 0; j < 17; j++) red[j][threadIdx.x] += red[j][threadIdx.x + s];
        __syncthreads();
    }
    if (threadIdx.x < 17)
        g_fix_part[(fi * 20 + blockIdx.y) * 17 + threadIdx.x] = red[threadIdx.x][0];
}

__global__ void fixup2_kernel(const float* __restrict__ bi2,
                              const float* __restrict__ br2,
                              const float* __restrict__ bu2) {
    const int fi = blockIdx.x;
    int cnt = g_fix_count; if (cnt > MAXFIX) cnt = MAXFIX;
    if (fi >= cnt) return;
    const int j = threadIdx.x;
    if (j >= 17) return;
    const int t = g_fix_list[fi];
    float s = 0.f;
    for (int p = 0; p < 20; p++) s += g_fix_part[(fi * 20 + p) * 17 + j];
    float bias = (j == 0) ? bi2[0] : (j < 9 ? br2[j - 1] : bu2[j - 9]);
    g_logits[t * 17 + j] = s + bias;
}

// ---------------- router ----------------
__global__ void router_kernel(float* __restrict__ out) {
    const int t = blockIdx.x * blockDim.x + threadIdx.x;
    if (t >= T_TOK) return;
    const float* l = g_logits + t * 17;
    const float l0 = l[0];
    const float imp = 1.f / (1.f + expf(-l0));
    out[IMP_OFF + t] = imp;
    const bool mask = imp > 0.5f;
    float lg[NEXP];
#pragma unroll
    for (int e = 0; e < NEXP; e++) lg[e] = mask ? l[1 + e] : l[9 + e];
    float m = lg[0];
#pragma unroll
    for (int e = 1; e < NEXP; e++) m = fmaxf(m, lg[e]);
    float p[NEXP], s = 0.f;
#pragma unroll
    for (int e = 0; e < NEXP; e++) { p[e] = expf(lg[e] - m); s += p[e]; }
#pragma unroll
    for (int e = 0; e < NEXP; e++) {
        p[e] = p[e] / s;
        out[PROB_OFF + (size_t)t * NEXP + e] = p[e];
    }
    int i0 = 0; float p0 = p[0];
#pragma unroll
    for (int e = 1; e < NEXP; e++) if (p[e] > p0) { p0 = p[e]; i0 = e; }
    int i1 = -1; float p1 = -1.f;
#pragma unroll
    for (int e = 0; e < NEXP; e++) if (e != i0 && p[e] > p1) { p1 = p[e]; i1 = e; }
    const float sn = p0 + p1;
    g_top_i[t] = i0 | (i1 << 8);
    g_top_p[t] = make_float2(p0 / sn, p1 / sn);
    atomicOr(&g_occ0, 1 << i0);
}

// ---------------- scatter ----------------
__global__ void scatter_kernel(float* __restrict__ out) {
    const int t = blockIdx.x * blockDim.x + threadIdx.x;
    if (t >= T_TOK) return;
    const int ii = g_top_i[t];
    const int i0 = ii & 255, i1 = (ii >> 8) & 255;
    const float2 pp = g_top_p[t];
    const int occ = g_occ0;
    size_t b0 = (size_t)(t * NEXP + i0) * CAP;
    out[DISP_OFF + b0] = 1.f;
    out[COMB_OFF + b0] = pp.x;
    const int pos1 = (occ >> i1) & 1;
    size_t b1 = (size_t)(t * NEXP + i1) * CAP + pos1;
    out[DISP_OFF + b1] = 1.f;
    out[COMB_OFF + b1] = pp.y;
}

// ---------------- finalize: aux loss ----------------
__global__ void finalize_kernel(float* __restrict__ out) {
    const int tid = threadIdx.x;
    __shared__ float sr[NEXP][256];
    __shared__ float si[NEXP][256];
    float rl[NEXP], il[NEXP];
#pragma unroll
    for (int e = 0; e < NEXP; e++) { rl[e] = 0.f; il[e] = 0.f; }
    for (int t = tid; t < T_TOK; t += 256) {
        const float l0 = g_logits[t * 17];
        const float mv = (1.f / (1.f + expf(-l0))) > 0.5f ? 1.f : 0.f;
#pragma unroll
        for (int e = 0; e < NEXP; e++) {
            const float pe = out[PROB_OFF + (size_t)t * NEXP + e];
            rl[e] += pe; il[e] += pe * mv;
        }
    }
#pragma unroll
    for (int e = 0; e < NEXP; e++) { sr[e][tid] = rl[e]; si[e][tid] = il[e]; }
    __syncthreads();
    for (int s = 128; s > 0; s >>= 1) {
        if (tid < s)
#pragma unroll
            for (int e = 0; e < NEXP; e++) { sr[e][tid] += sr[e][tid + s]; si[e][tid] += si[e][tid + s]; }
        __syncthreads();
    }
    if (tid == 0) {
        const float EPS = 1e-9f;
        float ent = 0.f, imp_sum[NEXP], tot = 0.f;
#pragma unroll
        for (int e = 0; e < NEXP; e++) {
            const float rppe = sr[e][0] / (float)T_TOK;
            ent += rppe * logf(rppe * (float)NEXP + EPS);
            imp_sum[e] = si[e][0] + EPS; tot += imp_sum[e];
        }
        float ih = 0.f;
#pragma unroll
        for (int e = 0; e < NEXP; e++) {
            const float ipe = imp_sum[e] / tot;
            ih -= ipe * logf(ipe + EPS);
        }
        out[AUX_OFF] = ent - 0.1f * (ih / logf((float)NEXP));
    }
}

// ---------------- launch ----------------
extern "C" void kernel_launch(void* const* d_in, const int* in_sizes, int n_in,
                              void* d_out, int out_size) {
    const float* x   = (const float*)d_in[0];
    const float* Wi1 = (const float*)d_in[1];
    const float* bi1 = (const float*)d_in[2];
    const float* Wi2 = (const float*)d_in[3];
    const float* bi2 = (const float*)d_in[4];
    const float* Wr1 = (const float*)d_in[5];
    const float* br1 = (const float*)d_in[6];
    const float* Wr2 = (const float*)d_in[7];
    const float* br2 = (const float*)d_in[8];
    const float* Wu1 = (const float*)d_in[9];
    const float* bu1 = (const float*)d_in[10];
    const float* Wu2 = (const float*)d_in[11];
    const float* bu2 = (const float*)d_in[12];
    float* out = (float*)d_out;

    cudaFuncSetAttribute(gemm1_mma_kernel, cudaFuncAttributeMaxDynamicSharedMemorySize, SMEM_GEMM);

    zero_kernel<<<2048, 256>>>((float4*)out, (unsigned int)(PROB_OFF / 4));
    split_x_kernel<<<2048, 256>>>((const float4*)x);
    split_w_kernel<<<dim3(NHID / 32, HDIM / 32), dim3(32, 8)>>>(Wi1, Wr1, Wu1);
    init_logits_kernel<<<T_TOK / 256, 256>>>(bi2, br2, bu2);
    gemm1_mma_kernel<<<dim3(NHID / 128, T_TOK / 128), 256, SMEM_GEMM>>>(bi1, br1, bu1, Wi2, Wr2, Wu2);
    flag_kernel<<<T_TOK / 256, 256>>>();
    fixup1_kernel<<<dim3(MAXFIX, 20), 256>>>(x, Wi1, bi1, Wr1, br1, Wu1, bu1, Wi2, Wr2, Wu2);
    fixup2_kernel<<<MAXFIX, 32>>>(bi2, br2, bu2);
    router_kernel<<<T_TOK / 256, 256>>>(out);
    scatter_kernel<<<T_TOK / 256, 256>>>(out);
    finalize_kernel<<<1, 256>>>(out);
}

// round 10
// speedup vs baseline: 2.0896x; 1.0479x over previous
#include <cuda_runtime.h>
#include <cuda_bf16.h>
#include <math.h>
#include <stdint.h>

#define T_TOK 4096
#define HDIM  2048
#define NEXP  8
#define CAP   1536
#define NHID  5120

#define DISP_OFF 0
#define COMB_OFF 50331648
#define PROB_OFF 100663296
#define AUX_OFF  100696064
#define IMP_OFF  100696065

#define TAU 3e-4f
#define MAXFIX 64

#define ZTOT 25165824u      // PROB_OFF/4 float4s to zero
#define ZCHUNK 19661u       // per gemm1 block

// ---------------- device scratch ----------------
__device__ float  g_logits[T_TOK * 17];
__device__ int    g_top_i[T_TOK];
__device__ float2 g_top_p[T_TOK];
__device__ int    g_occ0;
__device__ __nv_bfloat16 g_Xhi[(size_t)T_TOK * HDIM];
__device__ __nv_bfloat16 g_Xlo[(size_t)T_TOK * HDIM];
__device__ __nv_bfloat16 g_Whi[(size_t)NHID * HDIM];   // [n][k]
__device__ __nv_bfloat16 g_Wlo[(size_t)NHID * HDIM];
__device__ int    g_fix_count;
__device__ int    g_fix_list[MAXFIX];
__device__ float  g_fix_part[MAXFIX * 20 * 17];

// ---------------- helpers ----------------
__device__ __forceinline__ uint32_t smem_u32(const void* p) {
    uint32_t a;
    asm("{ .reg .u64 t; cvta.to.shared.u64 t, %1; cvt.u32.u64 %0, t; }" : "=r"(a) : "l"(p));
    return a;
}
#define SWZ(o) ((o) ^ (((o) >> 3) & 0x70))
#define CP_ASYNC16(dst, src) asm volatile("cp.async.cg.shared.global [%0], [%1], 16;" :: "r"(dst), "l"(src))
#define CP_COMMIT() asm volatile("cp.async.commit_group;" ::: "memory")
#define CP_WAIT(n)  asm volatile("cp.async.wait_group %0;" :: "n"(n) : "memory")

__device__ __forceinline__ void ldsm4(uint32_t& r0, uint32_t& r1, uint32_t& r2, uint32_t& r3, uint32_t addr) {
    asm volatile("ldmatrix.sync.aligned.m8n8.x4.shared.b16 {%0,%1,%2,%3}, [%4];"
        : "=r"(r0), "=r"(r1), "=r"(r2), "=r"(r3) : "r"(addr));
}
__device__ __forceinline__ void mma_bf16(float* d, uint32_t a0, uint32_t a1, uint32_t a2, uint32_t a3,
                                         uint32_t b0, uint32_t b1) {
    asm volatile("mma.sync.aligned.m16n8k16.row.col.f32.bf16.bf16.f32 "
        "{%0,%1,%2,%3}, {%4,%5,%6,%7}, {%8,%9}, {%0,%1,%2,%3};"
        : "+f"(d[0]), "+f"(d[1]), "+f"(d[2]), "+f"(d[3])
        : "r"(a0), "r"(a1), "r"(a2), "r"(a3), "r"(b0), "r"(b1));
}

// ---------------- bf16 hi/lo split ----------------
__device__ __forceinline__ void split1(float x, unsigned short& h, unsigned short& l) {
    __nv_bfloat16 hb = __float2bfloat16_rn(x);
    __nv_bfloat16 lb = __float2bfloat16_rn(x - __bfloat162float(hb));
    h = *(unsigned short*)&hb; l = *(unsigned short*)&lb;
}

__global__ void split_x_kernel(const float4* __restrict__ X) {
    const unsigned int n4 = (unsigned int)((size_t)T_TOK * HDIM / 4);
    unsigned int i = blockIdx.x * blockDim.x + threadIdx.x;
    unsigned int st = gridDim.x * blockDim.x;
    for (; i < n4; i += st) {
        float4 v = X[i];
        ushort4 ph, pl;
        split1(v.x, ph.x, pl.x); split1(v.y, ph.y, pl.y);
        split1(v.z, ph.z, pl.z); split1(v.w, ph.w, pl.w);
        *(ushort4*)(g_Xhi + (size_t)i * 4) = ph;
        *(ushort4*)(g_Xlo + (size_t)i * 4) = pl;
    }
}

__global__ void split_w_kernel(const float* __restrict__ Wi1,
                               const float* __restrict__ Wr1,
                               const float* __restrict__ Wu1) {
    __shared__ float tile[32][33];
    const int tx = threadIdx.x, ty = threadIdx.y;
    const int nb = blockIdx.x * 32, kb = blockIdx.y * 32;
    const float* W; int nl, ld;
    if (nb < 1024)      { W = Wi1; nl = nb;        ld = 1024; }
    else if (nb < 3072) { W = Wr1; nl = nb - 1024; ld = 2048; }
    else                { W = Wu1; nl = nb - 3072; ld = 2048; }
#pragma unroll
    for (int r = 0; r < 4; r++)
        tile[ty + 8 * r][tx] = W[(size_t)(kb + ty + 8 * r) * ld + nl + tx];
    __syncthreads();
#pragma unroll
    for (int r = 0; r < 4; r++) {
        const int n = ty + 8 * r;
        unsigned short h, l;
        split1(tile[tx][n], h, l);
        size_t o = (size_t)(nb + n) * HDIM + kb + tx;
        *(unsigned short*)(g_Whi + o) = h;
        *(unsigned short*)(g_Wlo + o) = l;
    }
}

// ---------------- init logits with biases + reset scalars ----------------
__global__ void init_logits_kernel(const float* __restrict__ bi2,
                                   const float* __restrict__ br2,
                                   const float* __restrict__ bu2) {
    const int t = blockIdx.x * blockDim.x + threadIdx.x;
    if (t == 0) { g_occ0 = 0; g_fix_count = 0; }
    if (t >= T_TOK) return;
    float* o = g_logits + t * 17;
    o[0] = bi2[0];
#pragma unroll
    for (int e = 0; e < NEXP; e++) o[1 + e] = br2[e];
#pragma unroll
    for (int e = 0; e < NEXP; e++) o[9 + e] = bu2[e];
}

// ---------------- GEMM1 via mma.sync bf16 (3-product hi/lo) + fused layer-2 epilogue
//                  + background zero-fill of disp/comb ----------------
#define BKH   64
#define STG   32768
#define NSTG  3
#define SMEM_GEMM (NSTG * STG)
#define KT_TOTAL 96
#define TPAD 132           // tile row stride (floats)

__device__ __forceinline__ void g1_load_stage(uint32_t sbase, int slot, int kt, int bm, int bn, int tid) {
    const int sec = kt >> 5;
    const int k0 = (kt & 31) * BKH;
    const __nv_bfloat16* Ap = (sec == 2) ? g_Xlo : g_Xhi;
    const __nv_bfloat16* Bp = (sec == 1) ? g_Wlo : g_Whi;
    uint32_t sA = sbase + slot * STG;
    uint32_t sB = sA + 16384;
#pragma unroll
    for (int it = 0; it < 4; it++) {
        int seg = it * 256 + tid;
        int row = seg >> 3, ks = seg & 7;
        CP_ASYNC16(sA + SWZ(row * 128 + ks * 16),
                   Ap + (size_t)(bm * 128 + row) * HDIM + k0 + ks * 8);
    }
#pragma unroll
    for (int it = 0; it < 4; it++) {
        int seg = it * 256 + tid;
        int row = seg >> 3, ks = seg & 7;
        CP_ASYNC16(sB + SWZ(row * 128 + ks * 16),
                   Bp + (size_t)(bn * 128 + row) * HDIM + k0 + ks * 8);
    }
    CP_COMMIT();
}

__global__ __launch_bounds__(256, 2)
void gemm1_mma_kernel(const float* __restrict__ bi1,
                      const float* __restrict__ br1,
                      const float* __restrict__ bu1,
                      const float* __restrict__ Wi2,
                      const float* __restrict__ Wr2,
                      const float* __restrict__ Wu2,
                      float4* __restrict__ zout) {
    extern __shared__ char smem[];
    __shared__ float bias_s[128];
    const uint32_t sbase = smem_u32(smem);
    const int tid = threadIdx.x, wid = tid >> 5, lane = tid & 31;
    const int wm = wid & 3, wn = wid >> 2;
    const int bn = blockIdx.x, bm = blockIdx.y;
    const int n0 = bn * 128;

    // zero-fill slice for this block
    const unsigned int bid = blockIdx.y * gridDim.x + blockIdx.x;
    unsigned int zi = bid * ZCHUNK + tid;
    unsigned int zend = bid * ZCHUNK + ZCHUNK;
    if (zend > ZTOT) zend = ZTOT;
    const float4 zv = make_float4(0.f, 0.f, 0.f, 0.f);

    int hsel, nl0;
    if (n0 < 1024)      { hsel = 0; nl0 = n0; }
    else if (n0 < 3072) { hsel = 1; nl0 = n0 - 1024; }
    else                { hsel = 2; nl0 = n0 - 3072; }

    if (tid < 128) {
        const float* bias = (hsel == 0) ? bi1 : (hsel == 1 ? br1 : bu1);
        bias_s[tid] = bias[nl0 + tid];
    }

    float d[2][8][4];
#pragma unroll
    for (int i = 0; i < 2; i++)
#pragma unroll
        for (int j = 0; j < 8; j++)
#pragma unroll
            for (int c = 0; c < 4; c++) d[i][j][c] = 0.f;

    g1_load_stage(sbase, 0, 0, bm, bn, tid);
    g1_load_stage(sbase, 1, 1, bm, bn, tid);

    const int lrow = lane & 15;
    const int lcol16 = (lane >> 4) * 16;

    for (int kt = 0; kt < KT_TOTAL; kt++) {
        if (kt + 2 < KT_TOTAL) { CP_WAIT(1); } else { CP_WAIT(0); }
        __syncthreads();
        if (kt + 2 < KT_TOTAL) g1_load_stage(sbase, (kt + 2) % NSTG, kt + 2, bm, bn, tid);

        // one background zero store per iteration
        if (zi < zend) { zout[zi] = zv; zi += 256; }

        const int slot = kt % NSTG;
        const uint32_t sA = sbase + slot * STG;
        const uint32_t sB = sA + 16384;
#pragma unroll
        for (int ks = 0; ks < 4; ks++) {
            uint32_t a[2][4];
#pragma unroll
            for (int im = 0; im < 2; im++) {
                int row = wm * 32 + im * 16 + lrow;
                ldsm4(a[im][0], a[im][1], a[im][2], a[im][3],
                      sA + SWZ(row * 128 + ks * 32 + lcol16));
            }
            uint32_t bfr[8][2];
#pragma unroll
            for (int ib = 0; ib < 4; ib++) {
                int row = wn * 64 + ib * 16 + lrow;
                uint32_t r0, r1, r2, r3;
                ldsm4(r0, r1, r2, r3, sB + SWZ(row * 128 + ks * 32 + lcol16));
                bfr[2 * ib][0] = r0;     bfr[2 * ib][1] = r2;
                bfr[2 * ib + 1][0] = r1; bfr[2 * ib + 1][1] = r3;
            }
#pragma unroll
            for (int im = 0; im < 2; im++)
#pragma unroll
                for (int jn = 0; jn < 8; jn++)
                    mma_bf16(d[im][jn], a[im][0], a[im][1], a[im][2], a[im][3],
                             bfr[jn][0], bfr[jn][1]);
        }
    }

    // finish any remaining zero stores (zend - start <= 19661 -> <=77 per thread, 96 already issued)
    while (zi < zend) { zout[zi] = zv; zi += 256; }

    // ---- fused epilogue: relu tile -> smem, then layer-2 partials -> atomicAdd g_logits ----
    __syncthreads();   // all warps done reading stage smem
    float* tile = (float*)smem;   // 128 x TPAD floats (67.6 KB <= 96 KB)
    const int r0 = lane >> 2;
    const int c0 = (lane & 3) * 2;
#pragma unroll
    for (int im = 0; im < 2; im++) {
        const int ml = wm * 32 + im * 16 + r0;
#pragma unroll
        for (int jn = 0; jn < 8; jn++) {
            const int nl = wn * 64 + jn * 8 + c0;
            const float b0 = bias_s[nl], b1 = bias_s[nl + 1];
            tile[ml * TPAD + nl]           = fmaxf(d[im][jn][0] + b0, 0.f);
            tile[ml * TPAD + nl + 1]       = fmaxf(d[im][jn][1] + b1, 0.f);
            tile[(ml + 8) * TPAD + nl]     = fmaxf(d[im][jn][2] + b0, 0.f);
            tile[(ml + 8) * TPAD + nl + 1] = fmaxf(d[im][jn][3] + b1, 0.f);
        }
    }
    __syncthreads();

    if (hsel == 0) {
        const float w0 = Wi2[nl0 + lane], w1 = Wi2[nl0 + lane + 32];
        const float w2 = Wi2[nl0 + lane + 64], w3 = Wi2[nl0 + lane + 96];
        for (int r = 0; r < 16; r++) {
            const int m = wid * 16 + r;
            const float* tr = tile + m * TPAD;
            float p = tr[lane] * w0 + tr[lane + 32] * w1 + tr[lane + 64] * w2 + tr[lane + 96] * w3;
#pragma unroll
            for (int off = 16; off > 0; off >>= 1) p += __shfl_xor_sync(0xffffffffu, p, off);
            if (lane == 0) atomicAdd(&g_logits[(size_t)(bm * 128 + m) * 17], p);
        }
    } else {
        const float* W2 = (hsel == 1) ? Wr2 : Wu2;
        const int jb = (hsel == 1) ? 1 : 9;
        float w[4][8];
#pragma unroll
        for (int q = 0; q < 4; q++) {
            const float* wp = W2 + (size_t)(nl0 + lane + 32 * q) * 8;
            float4 a4 = *(const float4*)wp;
            float4 b4 = *(const float4*)(wp + 4);
            w[q][0] = a4.x; w[q][1] = a4.y; w[q][2] = a4.z; w[q][3] = a4.w;
            w[q][4] = b4.x; w[q][5] = b4.y; w[q][6] = b4.z; w[q][7] = b4.w;
        }
        for (int r = 0; r < 16; r++) {
            const int m = wid * 16 + r;
            const float* tr = tile + m * TPAD;
            const float v0 = tr[lane], v1 = tr[lane + 32], v2 = tr[lane + 64], v3 = tr[lane + 96];
            float p[8];
#pragma unroll
            for (int e = 0; e < 8; e++)
                p[e] = v0 * w[0][e] + v1 * w[1][e] + v2 * w[2][e] + v3 * w[3][e];
#pragma unroll
            for (int e = 0; e < 8; e++)
#pragma unroll
                for (int off = 16; off > 0; off >>= 1)
                    p[e] += __shfl_xor_sync(0xffffffffu, p[e], off);
            if (lane == 0) {
                float* gl = g_logits + (size_t)(bm * 128 + m) * 17 + jb;
#pragma unroll
                for (int e = 0; e < 8; e++) atomicAdd(gl + e, p[e]);
            }
        }
    }
}

// ---------------- flag borderline tokens ----------------
__global__ void flag_kernel() {
    const int t = blockIdx.x * blockDim.x + threadIdx.x;
    if (t >= T_TOK) return;
    const float* l = g_logits + t * 17;
    const float l0 = l[0];
    bool flag = fabsf(l0) < TAU;
    const bool mask = l0 > 0.f;
    float lg[NEXP];
#pragma unroll
    for (int e = 0; e < NEXP; e++) lg[e] = mask ? l[1 + e] : l[9 + e];
    float v1 = -1e30f, v2 = -1e30f, v3 = -1e30f;
#pragma unroll
    for (int e = 0; e < NEXP; e++) {
        float v = lg[e];
        if (v > v1)      { v3 = v2; v2 = v1; v1 = v; }
        else if (v > v2) { v3 = v2; v2 = v; }
        else if (v > v3) { v3 = v; }
    }
    if (v1 - v2 < TAU || v2 - v3 < TAU) flag = true;
    if (flag) {
        int idx = atomicAdd(&g_fix_count, 1);
        if (idx < MAXFIX) g_fix_list[idx] = t;
    }
}

// ---------------- exact fp32 recompute for flagged tokens ----------------
__global__ void fixup1_kernel(const float* __restrict__ X,
                              const float* __restrict__ Wi1, const float* __restrict__ bi1,
                              const float* __restrict__ Wr1, const float* __restrict__ br1,
                              const float* __restrict__ Wu1, const float* __restrict__ bu1,
                              const float* __restrict__ Wi2,
                              const float* __restrict__ Wr2,
                              const float* __restrict__ Wu2) {
    const int fi = blockIdx.x;
    int cnt = g_fix_count; if (cnt > MAXFIX) cnt = MAXFIX;
    if (fi >= cnt) return;
    const int t = g_fix_list[fi];
    const int n = blockIdx.y * 256 + threadIdx.x;
    __shared__ float xs[HDIM];
    __shared__ float red[17][257];
    for (int k = threadIdx.x; k < HDIM; k += 256) xs[k] = X[(size_t)t * HDIM + k];
    __syncthreads();

    const float* W; const float* b; int nl, ld;
    if (n < 1024)      { W = Wi1; b = bi1; nl = n;        ld = 1024; }
    else if (n < 3072) { W = Wr1; b = br1; nl = n - 1024; ld = 2048; }
    else               { W = Wu1; b = bu1; nl = n - 3072; ld = 2048; }
    float acc = 0.f;
    for (int k = 0; k < HDIM; k++) acc = fmaf(xs[k], W[(size_t)k * ld + nl], acc);
    float hval = fmaxf(acc + b[nl], 0.f);

    float part[17];
#pragma unroll
    for (int j = 0; j < 17; j++) part[j] = 0.f;
    if (n < 1024) part[0] = hval * Wi2[n];
    else if (n < 3072) {
        const float* w = Wr2 + (size_t)(n - 1024) * 8;
#pragma unroll
        for (int e = 0; e < NEXP; e++) part[1 + e] = hval * w[e];
    } else {
        const float* w = Wu2 + (size_t)(n - 3072) * 8;
#pragma unroll
        for (int e = 0; e < NEXP; e++) part[9 + e] = hval * w[e];
    }
#pragma unroll
    for (int j = 0; j < 17; j++) red[j][threadIdx.x] = part[j];
    __syncthreads();
    for (int s = 128; s > 0; s >>= 1) {
        if (threadIdx.x < s)
#pragma unroll
            for (int j = 0; j < 17; j++) red[j][threadIdx.x] += red[j][threadIdx.x + s];
        __syncthreads();
    }
    if (threadIdx.x < 17)
        g_fix_part[(fi * 20 + blockIdx.y) * 17 + threadIdx.x] = red[threadIdx.x][0];
}

__global__ void fixup2_kernel(const float* __restrict__ bi2,
                              const float* __restrict__ br2,
                              const float* __restrict__ bu2) {
    const int fi = blockIdx.x;
    int cnt = g_fix_count; if (cnt > MAXFIX) cnt = MAXFIX;
    if (fi >= cnt) return;
    const int j = threadIdx.x;
    if (j >= 17) return;
    const int t = g_fix_list[fi];
    float s = 0.f;
    for (int p = 0; p < 20; p++) s += g_fix_part[(fi * 20 + p) * 17 + j];
    float bias = (j == 0) ? bi2[0] : (j < 9 ? br2[j - 1] : bu2[j - 9]);
    g_logits[t * 17 + j] = s + bias;
}

// ---------------- router ----------------
__global__ void router_kernel(float* __restrict__ out) {
    const int t = blockIdx.x * blockDim.x + threadIdx.x;
    if (t >= T_TOK) return;
    const float* l = g_logits + t * 17;
    const float l0 = l[0];
    const float imp = 1.f / (1.f + expf(-l0));
    out[IMP_OFF + t] = imp;
    const bool mask = imp > 0.5f;
    float lg[NEXP];
#pragma unroll
    for (int e = 0; e < NEXP; e++) lg[e] = mask ? l[1 + e] : l[9 + e];
    float m = lg[0];
#pragma unroll
    for (int e = 1; e < NEXP; e++) m = fmaxf(m, lg[e]);
    float p[NEXP], s = 0.f;
#pragma unroll
    for (int e = 0; e < NEXP; e++) { p[e] = expf(lg[e] - m); s += p[e]; }
#pragma unroll
    for (int e = 0; e < NEXP; e++) {
        p[e] = p[e] / s;
        out[PROB_OFF + (size_t)t * NEXP + e] = p[e];
    }
    int i0 = 0; float p0 = p[0];
#pragma unroll
    for (int e = 1; e < NEXP; e++) if (p[e] > p0) { p0 = p[e]; i0 = e; }
    int i1 = -1; float p1 = -1.f;
#pragma unroll
    for (int e = 0; e < NEXP; e++) if (e != i0 && p[e] > p1) { p1 = p[e]; i1 = e; }
    const float sn = p0 + p1;
    g_top_i[t] = i0 | (i1 << 8);
    g_top_p[t] = make_float2(p0 / sn, p1 / sn);
    atomicOr(&g_occ0, 1 << i0);
}

// ---------------- scatter ----------------
__global__ void scatter_kernel(float* __restrict__ out) {
    const int t = blockIdx.x * blockDim.x + threadIdx.x;
    if (t >= T_TOK) return;
    const int ii = g_top_i[t];
    const int i0 = ii & 255, i1 = (ii >> 8) & 255;
    const float2 pp = g_top_p[t];
    const int occ = g_occ0;
    size_t b0 = (size_t)(t * NEXP + i0) * CAP;
    out[DISP_OFF + b0] = 1.f;
    out[COMB_OFF + b0] = pp.x;
    const int pos1 = (occ >> i1) & 1;
    size_t b1 = (size_t)(t * NEXP + i1) * CAP + pos1;
    out[DISP_OFF + b1] = 1.f;
    out[COMB_OFF + b1] = pp.y;
}

// ---------------- finalize: aux loss ----------------
__global__ void finalize_kernel(float* __restrict__ out) {
    const int tid = threadIdx.x;
    __shared__ float sr[NEXP][256];
    __shared__ float si[NEXP][256];
    float rl[NEXP], il[NEXP];
#pragma unroll
    for (int e = 0; e < NEXP; e++) { rl[e] = 0.f; il[e] = 0.f; }
    for (int t = tid; t < T_TOK; t += 256) {
        const float l0 = g_logits[t * 17];
        const float mv = (1.f / (1.f + expf(-l0))) > 0.5f ? 1.f : 0.f;
#pragma unroll
        for (int e = 0; e < NEXP; e++) {
            const float pe = out[PROB_OFF + (size_t)t * NEXP + e];
            rl[e] += pe; il[e] += pe * mv;
        }
    }
#pragma unroll
    for (int e = 0; e < NEXP; e++) { sr[e][tid] = rl[e]; si[e][tid] = il[e]; }
    __syncthreads();
    for (int s = 128; s > 0; s >>= 1) {
        if (tid < s)
#pragma unroll
            for (int e = 0; e < NEXP; e++) { sr[e][tid] += sr[e][tid + s]; si[e][tid] += si[e][tid + s]; }
        __syncthreads();
    }
    if (tid == 0) {
        const float EPS = 1e-9f;
        float ent = 0.f, imp_sum[NEXP], tot = 0.f;
#pragma unroll
        for (int e = 0; e < NEXP; e++) {
            const float rppe = sr[e][0] / (float)T_TOK;
            ent += rppe * logf(rppe * (float)NEXP + EPS);
            imp_sum[e] = si[e][0] + EPS; tot += imp_sum[e];
        }
        float ih = 0.f;
#pragma unroll
        for (int e = 0; e < NEXP; e++) {
            const float ipe = imp_sum[e] / tot;
            ih -= ipe * logf(ipe + EPS);
        }
        out[AUX_OFF] = ent - 0.1f * (ih / logf((float)NEXP));
    }
}

// ---------------- launch ----------------
extern "C" void kernel_launch(void* const* d_in, const int* in_sizes, int n_in,
                              void* d_out, int out_size) {
    const float* x   = (const float*)d_in[0];
    const float* Wi1 = (const float*)d_in[1];
    const float* bi1 = (const float*)d_in[2];
    const float* Wi2 = (const float*)d_in[3];
    const float* bi2 = (const float*)d_in[4];
    const float* Wr1 = (const float*)d_in[5];
    const float* br1 = (const float*)d_in[6];
    const float* Wr2 = (const float*)d_in[7];
    const float* br2 = (const float*)d_in[8];
    const float* Wu1 = (const float*)d_in[9];
    const float* bu1 = (const float*)d_in[10];
    const float* Wu2 = (const float*)d_in[11];
    const float* bu2 = (const float*)d_in[12];
    float* out = (float*)d_out;

    cudaFuncSetAttribute(gemm1_mma_kernel, cudaFuncAttributeMaxDynamicSharedMemorySize, SMEM_GEMM);

    split_x_kernel<<<2048, 256>>>((const float4*)x);
    split_w_kernel<<<dim3(NHID / 32, HDIM / 32), dim3(32, 8)>>>(Wi1, Wr1, Wu1);
    init_logits_kernel<<<T_TOK / 256, 256>>>(bi2, br2, bu2);
    gemm1_mma_kernel<<<dim3(NHID / 128, T_TOK / 128), 256, SMEM_GEMM>>>(bi1, br1, bu1, Wi2, Wr2, Wu2, (float4*)out);
    flag_kernel<<<T_TOK / 256, 256>>>();
    fixup1_kernel<<<dim3(MAXFIX, 20), 256>>>(x, Wi1, bi1, Wr1, br1, Wu1, bu1, Wi2, Wr2, Wu2);
    fixup2_kernel<<<MAXFIX, 32>>>(bi2, br2, bu2);
    router_kernel<<<T_TOK / 256, 256>>>(out);
    scatter_kernel<<<T_TOK / 256, 256>>>(out);
    finalize_kernel<<<1, 256>>>(out);
}

// round 11
// speedup vs baseline: 2.1104x; 1.0100x over previous
#include <cuda_runtime.h>
#include <cuda_bf16.h>
#include <math.h>
#include <stdint.h>

#define T_TOK 4096
#define HDIM  2048
#define NEXP  8
#define CAP   1536
#define NHID  5120

#define DISP_OFF 0
#define COMB_OFF 50331648
#define PROB_OFF 100663296
#define AUX_OFF  100696064
#define IMP_OFF  100696065

#define TAU 3e-4f
#define MAXFIX 64

#define ZTOT 25165824u      // PROB_OFF/4 float4s to zero
#define ZCHUNK 19661u       // per gemm1 block

// ---------------- device scratch ----------------
__device__ float  g_logits[T_TOK * 17];
__device__ int    g_occ0;
__device__ int    g_bar;
__device__ __nv_bfloat16 g_Xhi[(size_t)T_TOK * HDIM];
__device__ __nv_bfloat16 g_Xlo[(size_t)T_TOK * HDIM];
__device__ __nv_bfloat16 g_Whi[(size_t)NHID * HDIM];   // [n][k]
__device__ __nv_bfloat16 g_Wlo[(size_t)NHID * HDIM];
__device__ int    g_fix_count;
__device__ int    g_fix_list[MAXFIX];
__device__ int    g_fix_idx[T_TOK];
__device__ float  g_fix_part[MAXFIX * 20 * 17];

// ---------------- helpers ----------------
__device__ __forceinline__ uint32_t smem_u32(const void* p) {
    uint32_t a;
    asm("{ .reg .u64 t; cvta.to.shared.u64 t, %1; cvt.u32.u64 %0, t; }" : "=r"(a) : "l"(p));
    return a;
}
#define SWZ(o) ((o) ^ (((o) >> 3) & 0x70))
#define CP_ASYNC16(dst, src) asm volatile("cp.async.cg.shared.global [%0], [%1], 16;" :: "r"(dst), "l"(src))
#define CP_COMMIT() asm volatile("cp.async.commit_group;" ::: "memory")
#define CP_WAIT(n)  asm volatile("cp.async.wait_group %0;" :: "n"(n) : "memory")

__device__ __forceinline__ void ldsm4(uint32_t& r0, uint32_t& r1, uint32_t& r2, uint32_t& r3, uint32_t addr) {
    asm volatile("ldmatrix.sync.aligned.m8n8.x4.shared.b16 {%0,%1,%2,%3}, [%4];"
        : "=r"(r0), "=r"(r1), "=r"(r2), "=r"(r3) : "r"(addr));
}
__device__ __forceinline__ void mma_bf16(float* d, uint32_t a0, uint32_t a1, uint32_t a2, uint32_t a3,
                                         uint32_t b0, uint32_t b1) {
    asm volatile("mma.sync.aligned.m16n8k16.row.col.f32.bf16.bf16.f32 "
        "{%0,%1,%2,%3}, {%4,%5,%6,%7}, {%8,%9}, {%0,%1,%2,%3};"
        : "+f"(d[0]), "+f"(d[1]), "+f"(d[2]), "+f"(d[3])
        : "r"(a0), "r"(a1), "r"(a2), "r"(a3), "r"(b0), "r"(b1));
}

// ---------------- bf16 hi/lo split ----------------
__device__ __forceinline__ void split1(float x, unsigned short& h, unsigned short& l) {
    __nv_bfloat16 hb = __float2bfloat16_rn(x);
    __nv_bfloat16 lb = __float2bfloat16_rn(x - __bfloat162float(hb));
    h = *(unsigned short*)&hb; l = *(unsigned short*)&lb;
}

// ---------------- prep: split_x + split_w + init (one launch) ----------------
#define PREP_XB 2048
#define PREP_WB 10240          // 160 * 64
#define PREP_IB 16
#define PREP_GRID (PREP_XB + PREP_WB + PREP_IB)

__global__ void prep_kernel(const float4* __restrict__ X,
                            const float* __restrict__ Wi1,
                            const float* __restrict__ Wr1,
                            const float* __restrict__ Wu1,
                            const float* __restrict__ bi2,
                            const float* __restrict__ br2,
                            const float* __restrict__ bu2) {
    __shared__ float tile[32][33];
    const int b = blockIdx.x;
    const int tid = threadIdx.x;

    if (b < PREP_XB) {
        const unsigned int n4 = (unsigned int)((size_t)T_TOK * HDIM / 4);
        unsigned int i = b * 256 + tid;
        const unsigned int st = PREP_XB * 256;
        for (; i < n4; i += st) {
            float4 v = X[i];
            ushort4 ph, pl;
            split1(v.x, ph.x, pl.x); split1(v.y, ph.y, pl.y);
            split1(v.z, ph.z, pl.z); split1(v.w, ph.w, pl.w);
            *(ushort4*)(g_Xhi + (size_t)i * 4) = ph;
            *(ushort4*)(g_Xlo + (size_t)i * 4) = pl;
        }
    } else if (b < PREP_XB + PREP_WB) {
        const int bw = b - PREP_XB;
        const int nb = (bw % 160) * 32;
        const int kb = (bw / 160) * 32;
        const int tx = tid & 31, ty = tid >> 5;
        const float* W; int nl, ld;
        if (nb < 1024)      { W = Wi1; nl = nb;        ld = 1024; }
        else if (nb < 3072) { W = Wr1; nl = nb - 1024; ld = 2048; }
        else                { W = Wu1; nl = nb - 3072; ld = 2048; }
#pragma unroll
        for (int r = 0; r < 4; r++)
            tile[ty + 8 * r][tx] = W[(size_t)(kb + ty + 8 * r) * ld + nl + tx];
        __syncthreads();
#pragma unroll
        for (int r = 0; r < 4; r++) {
            const int n = ty + 8 * r;
            unsigned short h, l;
            split1(tile[tx][n], h, l);
            size_t o = (size_t)(nb + n) * HDIM + kb + tx;
            *(unsigned short*)(g_Whi + o) = h;
            *(unsigned short*)(g_Wlo + o) = l;
        }
    } else {
        const int t = (b - PREP_XB - PREP_WB) * 256 + tid;
        if (t == 0) { g_occ0 = 0; g_fix_count = 0; g_bar = 0; }
        if (t < T_TOK) {
            g_fix_idx[t] = -1;
            float* o = g_logits + t * 17;
            o[0] = bi2[0];
#pragma unroll
            for (int e = 0; e < NEXP; e++) o[1 + e] = br2[e];
#pragma unroll
            for (int e = 0; e < NEXP; e++) o[9 + e] = bu2[e];
        }
    }
}

// ---------------- GEMM1 via mma.sync bf16 (3-product hi/lo) + fused layer-2 epilogue
//                  + background zero-fill of disp/comb ----------------
#define BKH   64
#define STG   32768
#define NSTG  3
#define SMEM_GEMM (NSTG * STG)
#define KT_TOTAL 96
#define TPAD 132

__device__ __forceinline__ void g1_load_stage(uint32_t sbase, int slot, int kt, int bm, int bn, int tid) {
    const int sec = kt >> 5;
    const int k0 = (kt & 31) * BKH;
    const __nv_bfloat16* Ap = (sec == 2) ? g_Xlo : g_Xhi;
    const __nv_bfloat16* Bp = (sec == 1) ? g_Wlo : g_Whi;
    uint32_t sA = sbase + slot * STG;
    uint32_t sB = sA + 16384;
#pragma unroll
    for (int it = 0; it < 4; it++) {
        int seg = it * 256 + tid;
        int row = seg >> 3, ks = seg & 7;
        CP_ASYNC16(sA + SWZ(row * 128 + ks * 16),
                   Ap + (size_t)(bm * 128 + row) * HDIM + k0 + ks * 8);
    }
#pragma unroll
    for (int it = 0; it < 4; it++) {
        int seg = it * 256 + tid;
        int row = seg >> 3, ks = seg & 7;
        CP_ASYNC16(sB + SWZ(row * 128 + ks * 16),
                   Bp + (size_t)(bn * 128 + row) * HDIM + k0 + ks * 8);
    }
    CP_COMMIT();
}

__global__ __launch_bounds__(256, 2)
void gemm1_mma_kernel(const float* __restrict__ bi1,
                      const float* __restrict__ br1,
                      const float* __restrict__ bu1,
                      const float* __restrict__ Wi2,
                      const float* __restrict__ Wr2,
                      const float* __restrict__ Wu2,
                      float4* __restrict__ zout) {
    extern __shared__ char smem[];
    __shared__ float bias_s[128];
    const uint32_t sbase = smem_u32(smem);
    const int tid = threadIdx.x, wid = tid >> 5, lane = tid & 31;
    const int wm = wid & 3, wn = wid >> 2;
    const int bn = blockIdx.x, bm = blockIdx.y;
    const int n0 = bn * 128;

    const unsigned int bid = blockIdx.y * gridDim.x + blockIdx.x;
    unsigned int zi = bid * ZCHUNK + tid;
    unsigned int zend = bid * ZCHUNK + ZCHUNK;
    if (zend > ZTOT) zend = ZTOT;
    const float4 zv = make_float4(0.f, 0.f, 0.f, 0.f);

    int hsel, nl0;
    if (n0 < 1024)      { hsel = 0; nl0 = n0; }
    else if (n0 < 3072) { hsel = 1; nl0 = n0 - 1024; }
    else                { hsel = 2; nl0 = n0 - 3072; }

    if (tid < 128) {
        const float* bias = (hsel == 0) ? bi1 : (hsel == 1 ? br1 : bu1);
        bias_s[tid] = bias[nl0 + tid];
    }

    float d[2][8][4];
#pragma unroll
    for (int i = 0; i < 2; i++)
#pragma unroll
        for (int j = 0; j < 8; j++)
#pragma unroll
            for (int c = 0; c < 4; c++) d[i][j][c] = 0.f;

    g1_load_stage(sbase, 0, 0, bm, bn, tid);
    g1_load_stage(sbase, 1, 1, bm, bn, tid);

    const int lrow = lane & 15;
    const int lcol16 = (lane >> 4) * 16;

    for (int kt = 0; kt < KT_TOTAL; kt++) {
        if (kt + 2 < KT_TOTAL) { CP_WAIT(1); } else { CP_WAIT(0); }
        __syncthreads();
        if (kt + 2 < KT_TOTAL) g1_load_stage(sbase, (kt + 2) % NSTG, kt + 2, bm, bn, tid);

        if (zi < zend) { zout[zi] = zv; zi += 256; }

        const int slot = kt % NSTG;
        const uint32_t sA = sbase + slot * STG;
        const uint32_t sB = sA + 16384;
#pragma unroll
        for (int ks = 0; ks < 4; ks++) {
            uint32_t a[2][4];
#pragma unroll
            for (int im = 0; im < 2; im++) {
                int row = wm * 32 + im * 16 + lrow;
                ldsm4(a[im][0], a[im][1], a[im][2], a[im][3],
                      sA + SWZ(row * 128 + ks * 32 + lcol16));
            }
            uint32_t bfr[8][2];
#pragma unroll
            for (int ib = 0; ib < 4; ib++) {
                int row = wn * 64 + ib * 16 + lrow;
                uint32_t r0, r1, r2, r3;
                ldsm4(r0, r1, r2, r3, sB + SWZ(row * 128 + ks * 32 + lcol16));
                bfr[2 * ib][0] = r0;     bfr[2 * ib][1] = r2;
                bfr[2 * ib + 1][0] = r1; bfr[2 * ib + 1][1] = r3;
            }
#pragma unroll
            for (int im = 0; im < 2; im++)
#pragma unroll
                for (int jn = 0; jn < 8; jn++)
                    mma_bf16(d[im][jn], a[im][0], a[im][1], a[im][2], a[im][3],
                             bfr[jn][0], bfr[jn][1]);
        }
    }

    while (zi < zend) { zout[zi] = zv; zi += 256; }

    // ---- fused epilogue ----
    __syncthreads();
    float* tile = (float*)smem;
    const int r0 = lane >> 2;
    const int c0 = (lane & 3) * 2;
#pragma unroll
    for (int im = 0; im < 2; im++) {
        const int ml = wm * 32 + im * 16 + r0;
#pragma unroll
        for (int jn = 0; jn < 8; jn++) {
            const int nl = wn * 64 + jn * 8 + c0;
            const float b0 = bias_s[nl], b1 = bias_s[nl + 1];
            tile[ml * TPAD + nl]           = fmaxf(d[im][jn][0] + b0, 0.f);
            tile[ml * TPAD + nl + 1]       = fmaxf(d[im][jn][1] + b1, 0.f);
            tile[(ml + 8) * TPAD + nl]     = fmaxf(d[im][jn][2] + b0, 0.f);
            tile[(ml + 8) * TPAD + nl + 1] = fmaxf(d[im][jn][3] + b1, 0.f);
        }
    }
    __syncthreads();

    if (hsel == 0) {
        const float w0 = Wi2[nl0 + lane], w1 = Wi2[nl0 + lane + 32];
        const float w2 = Wi2[nl0 + lane + 64], w3 = Wi2[nl0 + lane + 96];
        for (int r = 0; r < 16; r++) {
            const int m = wid * 16 + r;
            const float* tr = tile + m * TPAD;
            float p = tr[lane] * w0 + tr[lane + 32] * w1 + tr[lane + 64] * w2 + tr[lane + 96] * w3;
#pragma unroll
            for (int off = 16; off > 0; off >>= 1) p += __shfl_xor_sync(0xffffffffu, p, off);
            if (lane == 0) atomicAdd(&g_logits[(size_t)(bm * 128 + m) * 17], p);
        }
    } else {
        const float* W2 = (hsel == 1) ? Wr2 : Wu2;
        const int jb = (hsel == 1) ? 1 : 9;
        float w[4][8];
#pragma unroll
        for (int q = 0; q < 4; q++) {
            const float* wp = W2 + (size_t)(nl0 + lane + 32 * q) * 8;
            float4 a4 = *(const float4*)wp;
            float4 b4 = *(const float4*)(wp + 4);
            w[q][0] = a4.x; w[q][1] = a4.y; w[q][2] = a4.z; w[q][3] = a4.w;
            w[q][4] = b4.x; w[q][5] = b4.y; w[q][6] = b4.z; w[q][7] = b4.w;
        }
        for (int r = 0; r < 16; r++) {
            const int m = wid * 16 + r;
            const float* tr = tile + m * TPAD;
            const float v0 = tr[lane], v1 = tr[lane + 32], v2 = tr[lane + 64], v3 = tr[lane + 96];
            float p[8];
#pragma unroll
            for (int e = 0; e < 8; e++)
                p[e] = v0 * w[0][e] + v1 * w[1][e] + v2 * w[2][e] + v3 * w[3][e];
#pragma unroll
            for (int e = 0; e < 8; e++)
#pragma unroll
                for (int off = 16; off > 0; off >>= 1)
                    p[e] += __shfl_xor_sync(0xffffffffu, p[e], off);
            if (lane == 0) {
                float* gl = g_logits + (size_t)(bm * 128 + m) * 17 + jb;
#pragma unroll
                for (int e = 0; e < 8; e++) atomicAdd(gl + e, p[e]);
            }
        }
    }
}

// ---------------- flag borderline tokens ----------------
__global__ void flag_kernel() {
    const int t = blockIdx.x * blockDim.x + threadIdx.x;
    if (t >= T_TOK) return;
    const float* l = g_logits + t * 17;
    const float l0 = l[0];
    bool flag = fabsf(l0) < TAU;
    const bool mask = l0 > 0.f;
    float lg[NEXP];
#pragma unroll
    for (int e = 0; e < NEXP; e++) lg[e] = mask ? l[1 + e] : l[9 + e];
    float v1 = -1e30f, v2 = -1e30f, v3 = -1e30f;
#pragma unroll
    for (int e = 0; e < NEXP; e++) {
        float v = lg[e];
        if (v > v1)      { v3 = v2; v2 = v1; v1 = v; }
        else if (v > v2) { v3 = v2; v2 = v; }
        else if (v > v3) { v3 = v; }
    }
    if (v1 - v2 < TAU || v2 - v3 < TAU) flag = true;
    if (flag) {
        int idx = atomicAdd(&g_fix_count, 1);
        if (idx < MAXFIX) { g_fix_list[idx] = t; g_fix_idx[t] = idx; }
    }
}

// ---------------- exact fp32 recompute for flagged tokens ----------------
__global__ void fixup1_kernel(const float* __restrict__ X,
                              const float* __restrict__ Wi1, const float* __restrict__ bi1,
                              const float* __restrict__ Wr1, const float* __restrict__ br1,
                              const float* __restrict__ Wu1, const float* __restrict__ bu1,
                              const float* __restrict__ Wi2,
                              const float* __restrict__ Wr2,
                              const float* __restrict__ Wu2) {
    const int fi = blockIdx.x;
    int cnt = g_fix_count; if (cnt > MAXFIX) cnt = MAXFIX;
    if (fi >= cnt) return;
    const int t = g_fix_list[fi];
    const int n = blockIdx.y * 256 + threadIdx.x;
    __shared__ float xs[HDIM];
    __shared__ float red[17][257];
    for (int k = threadIdx.x; k < HDIM; k += 256) xs[k] = X[(size_t)t * HDIM + k];
    __syncthreads();

    const float* W; const float* b; int nl, ld;
    if (n < 1024)      { W = Wi1; b = bi1; nl = n;        ld = 1024; }
    else if (n < 3072) { W = Wr1; b = br1; nl = n - 1024; ld = 2048; }
    else               { W = Wu1; b = bu1; nl = n - 3072; ld = 2048; }
    float acc = 0.f;
    for (int k = 0; k < HDIM; k++) acc = fmaf(xs[k], W[(size_t)k * ld + nl], acc);
    float hval = fmaxf(acc + b[nl], 0.f);

    float part[17];
#pragma unroll
    for (int j = 0; j < 17; j++) part[j] = 0.f;
    if (n < 1024) part[0] = hval * Wi2[n];
    else if (n < 3072) {
        const float* w = Wr2 + (size_t)(n - 1024) * 8;
#pragma unroll
        for (int e = 0; e < NEXP; e++) part[1 + e] = hval * w[e];
    } else {
        const float* w = Wu2 + (size_t)(n - 3072) * 8;
#pragma unroll
        for (int e = 0; e < NEXP; e++) part[9 + e] = hval * w[e];
    }
#pragma unroll
    for (int j = 0; j < 17; j++) red[j][threadIdx.x] = part[j];
    __syncthreads();
    for (int s = 128; s > 0; s >>= 1) {
        if (threadIdx.x < s)
#pragma unroll
            for (int j = 0; j < 17; j++) red[j][threadIdx.x] += red[j][threadIdx.x + s];
        __syncthreads();
    }
    if (threadIdx.x < 17)
        g_fix_part[(fi * 20 + blockIdx.y) * 17 + threadIdx.x] = red[threadIdx.x][0];
}

// ---------------- fused: fixup2 + router + scatter + finalize ----------------
__global__ void router_fused_kernel(float* __restrict__ out,
                                    const float* __restrict__ bi2,
                                    const float* __restrict__ br2,
                                    const float* __restrict__ bu2) {
    const int tid = threadIdx.x;
    const int t = blockIdx.x * 256 + tid;

    // --- gather (possibly fixed) logits ---
    float l[17];
    const int fidx = g_fix_idx[t];
    if (fidx >= 0) {
#pragma unroll
        for (int j = 0; j < 17; j++) {
            float s = 0.f;
            for (int p = 0; p < 20; p++) s += g_fix_part[(fidx * 20 + p) * 17 + j];
            l[j] = s + ((j == 0) ? bi2[0] : (j < 9 ? br2[j - 1] : bu2[j - 9]));
        }
    } else {
#pragma unroll
        for (int j = 0; j < 17; j++) l[j] = g_logits[t * 17 + j];
    }

    // --- router ---
    const float imp = 1.f / (1.f + expf(-l[0]));
    out[IMP_OFF + t] = imp;
    const bool mask = imp > 0.5f;
    float lg[NEXP];
#pragma unroll
    for (int e = 0; e < NEXP; e++) lg[e] = mask ? l[1 + e] : l[9 + e];
    float m = lg[0];
#pragma unroll
    for (int e = 1; e < NEXP; e++) m = fmaxf(m, lg[e]);
    float p[NEXP], s = 0.f;
#pragma unroll
    for (int e = 0; e < NEXP; e++) { p[e] = expf(lg[e] - m); s += p[e]; }
#pragma unroll
    for (int e = 0; e < NEXP; e++) {
        p[e] = p[e] / s;
        out[PROB_OFF + (size_t)t * NEXP + e] = p[e];
    }
    int i0 = 0; float p0 = p[0];
#pragma unroll
    for (int e = 1; e < NEXP; e++) if (p[e] > p0) { p0 = p[e]; i0 = e; }
    int i1 = -1; float p1 = -1.f;
#pragma unroll
    for (int e = 0; e < NEXP; e++) if (e != i0 && p[e] > p1) { p1 = p[e]; i1 = e; }
    const float sn = p0 + p1;
    atomicOr(&g_occ0, 1 << i0);

    // --- software grid barrier (16 blocks, all resident) ---
    __threadfence();
    __syncthreads();
    if (tid == 0) {
        atomicAdd(&g_bar, 1);
        while (atomicAdd(&g_bar, 0) < (int)gridDim.x) { }
    }
    __syncthreads();

    // --- scatter ---
    const int occ = *(volatile int*)&g_occ0;
    size_t b0 = (size_t)(t * NEXP + i0) * CAP;
    out[DISP_OFF + b0] = 1.f;
    out[COMB_OFF + b0] = p0 / sn;
    const int pos1 = (occ >> i1) & 1;
    size_t b1 = (size_t)(t * NEXP + i1) * CAP + pos1;
    out[DISP_OFF + b1] = 1.f;
    out[COMB_OFF + b1] = p1 / sn;

    // --- finalize (block 0) ---
    if (blockIdx.x == 0) {
        __shared__ float sr[NEXP][256];
        __shared__ float si[NEXP][256];
        float rl[NEXP], il[NEXP];
#pragma unroll
        for (int e = 0; e < NEXP; e++) { rl[e] = 0.f; il[e] = 0.f; }
        for (int tt = tid; tt < T_TOK; tt += 256) {
            const float mv = out[IMP_OFF + tt] > 0.5f ? 1.f : 0.f;
#pragma unroll
            for (int e = 0; e < NEXP; e++) {
                const float pe = out[PROB_OFF + (size_t)tt * NEXP + e];
                rl[e] += pe; il[e] += pe * mv;
            }
        }
#pragma unroll
        for (int e = 0; e < NEXP; e++) { sr[e][tid] = rl[e]; si[e][tid] = il[e]; }
        __syncthreads();
        for (int st2 = 128; st2 > 0; st2 >>= 1) {
            if (tid < st2)
#pragma unroll
                for (int e = 0; e < NEXP; e++) { sr[e][tid] += sr[e][tid + st2]; si[e][tid] += si[e][tid + st2]; }
            __syncthreads();
        }
        if (tid == 0) {
            const float EPS = 1e-9f;
            float ent = 0.f, imp_sum[NEXP], tot = 0.f;
#pragma unroll
            for (int e = 0; e < NEXP; e++) {
                const float rppe = sr[e][0] / (float)T_TOK;
                ent += rppe * logf(rppe * (float)NEXP + EPS);
                imp_sum[e] = si[e][0] + EPS; tot += imp_sum[e];
            }
            float ih = 0.f;
#pragma unroll
            for (int e = 0; e < NEXP; e++) {
                const float ipe = imp_sum[e] / tot;
                ih -= ipe * logf(ipe + EPS);
            }
            out[AUX_OFF] = ent - 0.1f * (ih / logf((float)NEXP));
        }
    }
}

// ---------------- launch ----------------
extern "C" void kernel_launch(void* const* d_in, const int* in_sizes, int n_in,
                              void* d_out, int out_size) {
    const float* x   = (const float*)d_in[0];
    const float* Wi1 = (const float*)d_in[1];
    const float* bi1 = (const float*)d_in[2];
    const float* Wi2 = (const float*)d_in[3];
    const float* bi2 = (const float*)d_in[4];
    const float* Wr1 = (const float*)d_in[5];
    const float* br1 = (const float*)d_in[6];
    const float* Wr2 = (const float*)d_in[7];
    const float* br2 = (const float*)d_in[8];
    const float* Wu1 = (const float*)d_in[9];
    const float* bu1 = (const float*)d_in[10];
    const float* Wu2 = (const float*)d_in[11];
    const float* bu2 = (const float*)d_in[12];
    float* out = (float*)d_out;

    cudaFuncSetAttribute(gemm1_mma_kernel, cudaFuncAttributeMaxDynamicSharedMemorySize, SMEM_GEMM);

    prep_kernel<<<PREP_GRID, 256>>>((const float4*)x, Wi1, Wr1, Wu1, bi2, br2, bu2);
    gemm1_mma_kernel<<<dim3(NHID / 128, T_TOK / 128), 256, SMEM_GEMM>>>(bi1, br1, bu1, Wi2, Wr2, Wu2, (float4*)out);
    flag_kernel<<<T_TOK / 256, 256>>>();
    fixup1_kernel<<<dim3(MAXFIX, 20), 256>>>(x, Wi1, bi1, Wr1, br1, Wu1, bu1, Wi2, Wr2, Wu2);
    router_fused_kernel<<<T_TOK / 256, 256>>>(out, bi2, br2, bu2);
}

// round 12
// speedup vs baseline: 2.5311x; 1.1993x over previous
#include <cuda_runtime.h>
#include <cuda_bf16.h>
#include <math.h>
#include <stdint.h>

#define T_TOK 4096
#define HDIM  2048
#define NEXP  8
#define CAP   1536
#define NHID  5120

#define DISP_OFF 0
#define COMB_OFF 50331648
#define PROB_OFF 100663296
#define AUX_OFF  100696064
#define IMP_OFF  100696065

#define TAU 3e-4f
#define MAXFIX 64
#define KSPLIT 8
#define KSEG 256            // HDIM / KSPLIT

#define ZTOT 25165824u
#define ZCHUNK 19661u

// ---------------- device scratch ----------------
__device__ float  g_logits[T_TOK * 17];
__device__ int    g_occ0;
__device__ int    g_bar;
__device__ __nv_bfloat16 g_Xhi[(size_t)T_TOK * HDIM];
__device__ __nv_bfloat16 g_Xlo[(size_t)T_TOK * HDIM];
__device__ __nv_bfloat16 g_Whi[(size_t)NHID * HDIM];   // [n][k]
__device__ __nv_bfloat16 g_Wlo[(size_t)NHID * HDIM];
__device__ int    g_fix_count;
__device__ int    g_fix_list[MAXFIX];
__device__ int    g_fix_idx[T_TOK];
__device__ float  g_fix_part[MAXFIX * 20 * 17];
__device__ float  g_fixh[MAXFIX * KSPLIT * NHID];      // partial dots, 10.5 MB

// ---------------- helpers ----------------
__device__ __forceinline__ uint32_t smem_u32(const void* p) {
    uint32_t a;
    asm("{ .reg .u64 t; cvta.to.shared.u64 t, %1; cvt.u32.u64 %0, t; }" : "=r"(a) : "l"(p));
    return a;
}
#define SWZ(o) ((o) ^ (((o) >> 3) & 0x70))
#define CP_ASYNC16(dst, src) asm volatile("cp.async.cg.shared.global [%0], [%1], 16;" :: "r"(dst), "l"(src))
#define CP_COMMIT() asm volatile("cp.async.commit_group;" ::: "memory")
#define CP_WAIT(n)  asm volatile("cp.async.wait_group %0;" :: "n"(n) : "memory")

__device__ __forceinline__ void ldsm4(uint32_t& r0, uint32_t& r1, uint32_t& r2, uint32_t& r3, uint32_t addr) {
    asm volatile("ldmatrix.sync.aligned.m8n8.x4.shared.b16 {%0,%1,%2,%3}, [%4];"
        : "=r"(r0), "=r"(r1), "=r"(r2), "=r"(r3) : "r"(addr));
}
__device__ __forceinline__ void mma_bf16(float* d, uint32_t a0, uint32_t a1, uint32_t a2, uint32_t a3,
                                         uint32_t b0, uint32_t b1) {
    asm volatile("mma.sync.aligned.m16n8k16.row.col.f32.bf16.bf16.f32 "
        "{%0,%1,%2,%3}, {%4,%5,%6,%7}, {%8,%9}, {%0,%1,%2,%3};"
        : "+f"(d[0]), "+f"(d[1]), "+f"(d[2]), "+f"(d[3])
        : "r"(a0), "r"(a1), "r"(a2), "r"(a3), "r"(b0), "r"(b1));
}

// ---------------- bf16 hi/lo split ----------------
__device__ __forceinline__ void split1(float x, unsigned short& h, unsigned short& l) {
    __nv_bfloat16 hb = __float2bfloat16_rn(x);
    __nv_bfloat16 lb = __float2bfloat16_rn(x - __bfloat162float(hb));
    h = *(unsigned short*)&hb; l = *(unsigned short*)&lb;
}

// ---------------- prep: split_x + split_w + init (one launch) ----------------
#define PREP_XB 2048
#define PREP_WB 10240
#define PREP_IB 16
#define PREP_GRID (PREP_XB + PREP_WB + PREP_IB)

__global__ void prep_kernel(const float4* __restrict__ X,
                            const float* __restrict__ Wi1,
                            const float* __restrict__ Wr1,
                            const float* __restrict__ Wu1,
                            const float* __restrict__ bi2,
                            const float* __restrict__ br2,
                            const float* __restrict__ bu2) {
    __shared__ float tile[32][33];
    const int b = blockIdx.x;
    const int tid = threadIdx.x;

    if (b < PREP_XB) {
        const unsigned int n4 = (unsigned int)((size_t)T_TOK * HDIM / 4);
        unsigned int i = b * 256 + tid;
        const unsigned int st = PREP_XB * 256;
        for (; i < n4; i += st) {
            float4 v = X[i];
            ushort4 ph, pl;
            split1(v.x, ph.x, pl.x); split1(v.y, ph.y, pl.y);
            split1(v.z, ph.z, pl.z); split1(v.w, ph.w, pl.w);
            *(ushort4*)(g_Xhi + (size_t)i * 4) = ph;
            *(ushort4*)(g_Xlo + (size_t)i * 4) = pl;
        }
    } else if (b < PREP_XB + PREP_WB) {
        const int bw = b - PREP_XB;
        const int nb = (bw % 160) * 32;
        const int kb = (bw / 160) * 32;
        const int tx = tid & 31, ty = tid >> 5;
        const float* W; int nl, ld;
        if (nb < 1024)      { W = Wi1; nl = nb;        ld = 1024; }
        else if (nb < 3072) { W = Wr1; nl = nb - 1024; ld = 2048; }
        else                { W = Wu1; nl = nb - 3072; ld = 2048; }
#pragma unroll
        for (int r = 0; r < 4; r++)
            tile[ty + 8 * r][tx] = W[(size_t)(kb + ty + 8 * r) * ld + nl + tx];
        __syncthreads();
#pragma unroll
        for (int r = 0; r < 4; r++) {
            const int n = ty + 8 * r;
            unsigned short h, l;
            split1(tile[tx][n], h, l);
            size_t o = (size_t)(nb + n) * HDIM + kb + tx;
            *(unsigned short*)(g_Whi + o) = h;
            *(unsigned short*)(g_Wlo + o) = l;
        }
    } else {
        const int t = (b - PREP_XB - PREP_WB) * 256 + tid;
        if (t == 0) { g_occ0 = 0; g_fix_count = 0; g_bar = 0; }
        if (t < T_TOK) {
            g_fix_idx[t] = -1;
            float* o = g_logits + t * 17;
            o[0] = bi2[0];
#pragma unroll
            for (int e = 0; e < NEXP; e++) o[1 + e] = br2[e];
#pragma unroll
            for (int e = 0; e < NEXP; e++) o[9 + e] = bu2[e];
        }
    }
}

// ---------------- GEMM1 + fused layer-2 epilogue + background zero-fill ----------------
#define BKH   64
#define STG   32768
#define NSTG  3
#define SMEM_GEMM (NSTG * STG)
#define KT_TOTAL 96
#define TPAD 132

__device__ __forceinline__ void g1_load_stage(uint32_t sbase, int slot, int kt, int bm, int bn, int tid) {
    const int sec = kt >> 5;
    const int k0 = (kt & 31) * BKH;
    const __nv_bfloat16* Ap = (sec == 2) ? g_Xlo : g_Xhi;
    const __nv_bfloat16* Bp = (sec == 1) ? g_Wlo : g_Whi;
    uint32_t sA = sbase + slot * STG;
    uint32_t sB = sA + 16384;
#pragma unroll
    for (int it = 0; it < 4; it++) {
        int seg = it * 256 + tid;
        int row = seg >> 3, ks = seg & 7;
        CP_ASYNC16(sA + SWZ(row * 128 + ks * 16),
                   Ap + (size_t)(bm * 128 + row) * HDIM + k0 + ks * 8);
    }
#pragma unroll
    for (int it = 0; it < 4; it++) {
        int seg = it * 256 + tid;
        int row = seg >> 3, ks = seg & 7;
        CP_ASYNC16(sB + SWZ(row * 128 + ks * 16),
                   Bp + (size_t)(bn * 128 + row) * HDIM + k0 + ks * 8);
    }
    CP_COMMIT();
}

__global__ __launch_bounds__(256, 2)
void gemm1_mma_kernel(const float* __restrict__ bi1,
                      const float* __restrict__ br1,
                      const float* __restrict__ bu1,
                      const float* __restrict__ Wi2,
                      const float* __restrict__ Wr2,
                      const float* __restrict__ Wu2,
                      float4* __restrict__ zout) {
    extern __shared__ char smem[];
    __shared__ float bias_s[128];
    const uint32_t sbase = smem_u32(smem);
    const int tid = threadIdx.x, wid = tid >> 5, lane = tid & 31;
    const int wm = wid & 3, wn = wid >> 2;
    const int bn = blockIdx.x, bm = blockIdx.y;
    const int n0 = bn * 128;

    const unsigned int bid = blockIdx.y * gridDim.x + blockIdx.x;
    unsigned int zi = bid * ZCHUNK + tid;
    unsigned int zend = bid * ZCHUNK + ZCHUNK;
    if (zend > ZTOT) zend = ZTOT;
    const float4 zv = make_float4(0.f, 0.f, 0.f, 0.f);

    int hsel, nl0;
    if (n0 < 1024)      { hsel = 0; nl0 = n0; }
    else if (n0 < 3072) { hsel = 1; nl0 = n0 - 1024; }
    else                { hsel = 2; nl0 = n0 - 3072; }

    if (tid < 128) {
        const float* bias = (hsel == 0) ? bi1 : (hsel == 1 ? br1 : bu1);
        bias_s[tid] = bias[nl0 + tid];
    }

    float d[2][8][4];
#pragma unroll
    for (int i = 0; i < 2; i++)
#pragma unroll
        for (int j = 0; j < 8; j++)
#pragma unroll
            for (int c = 0; c < 4; c++) d[i][j][c] = 0.f;

    g1_load_stage(sbase, 0, 0, bm, bn, tid);
    g1_load_stage(sbase, 1, 1, bm, bn, tid);

    const int lrow = lane & 15;
    const int lcol16 = (lane >> 4) * 16;

    for (int kt = 0; kt < KT_TOTAL; kt++) {
        if (kt + 2 < KT_TOTAL) { CP_WAIT(1); } else { CP_WAIT(0); }
        __syncthreads();
        if (kt + 2 < KT_TOTAL) g1_load_stage(sbase, (kt + 2) % NSTG, kt + 2, bm, bn, tid);

        if (zi < zend) { zout[zi] = zv; zi += 256; }

        const int slot = kt % NSTG;
        const uint32_t sA = sbase + slot * STG;
        const uint32_t sB = sA + 16384;
#pragma unroll
        for (int ks = 0; ks < 4; ks++) {
            uint32_t a[2][4];
#pragma unroll
            for (int im = 0; im < 2; im++) {
                int row = wm * 32 + im * 16 + lrow;
                ldsm4(a[im][0], a[im][1], a[im][2], a[im][3],
                      sA + SWZ(row * 128 + ks * 32 + lcol16));
            }
            uint32_t bfr[8][2];
#pragma unroll
            for (int ib = 0; ib < 4; ib++) {
                int row = wn * 64 + ib * 16 + lrow;
                uint32_t r0, r1, r2, r3;
                ldsm4(r0, r1, r2, r3, sB + SWZ(row * 128 + ks * 32 + lcol16));
                bfr[2 * ib][0] = r0;     bfr[2 * ib][1] = r2;
                bfr[2 * ib + 1][0] = r1; bfr[2 * ib + 1][1] = r3;
            }
#pragma unroll
            for (int im = 0; im < 2; im++)
#pragma unroll
                for (int jn = 0; jn < 8; jn++)
                    mma_bf16(d[im][jn], a[im][0], a[im][1], a[im][2], a[im][3],
                             bfr[jn][0], bfr[jn][1]);
        }
    }

    while (zi < zend) { zout[zi] = zv; zi += 256; }

    // ---- fused epilogue ----
    __syncthreads();
    float* tile = (float*)smem;
    const int r0 = lane >> 2;
    const int c0 = (lane & 3) * 2;
#pragma unroll
    for (int im = 0; im < 2; im++) {
        const int ml = wm * 32 + im * 16 + r0;
#pragma unroll
        for (int jn = 0; jn < 8; jn++) {
            const int nl = wn * 64 + jn * 8 + c0;
            const float b0 = bias_s[nl], b1 = bias_s[nl + 1];
            tile[ml * TPAD + nl]           = fmaxf(d[im][jn][0] + b0, 0.f);
            tile[ml * TPAD + nl + 1]       = fmaxf(d[im][jn][1] + b1, 0.f);
            tile[(ml + 8) * TPAD + nl]     = fmaxf(d[im][jn][2] + b0, 0.f);
            tile[(ml + 8) * TPAD + nl + 1] = fmaxf(d[im][jn][3] + b1, 0.f);
        }
    }
    __syncthreads();

    if (hsel == 0) {
        const float w0 = Wi2[nl0 + lane], w1 = Wi2[nl0 + lane + 32];
        const float w2 = Wi2[nl0 + lane + 64], w3 = Wi2[nl0 + lane + 96];
        for (int r = 0; r < 16; r++) {
            const int m = wid * 16 + r;
            const float* tr = tile + m * TPAD;
            float p = tr[lane] * w0 + tr[lane + 32] * w1 + tr[lane + 64] * w2 + tr[lane + 96] * w3;
#pragma unroll
            for (int off = 16; off > 0; off >>= 1) p += __shfl_xor_sync(0xffffffffu, p, off);
            if (lane == 0) atomicAdd(&g_logits[(size_t)(bm * 128 + m) * 17], p);
        }
    } else {
        const float* W2 = (hsel == 1) ? Wr2 : Wu2;
        const int jb = (hsel == 1) ? 1 : 9;
        float w[4][8];
#pragma unroll
        for (int q = 0; q < 4; q++) {
            const float* wp = W2 + (size_t)(nl0 + lane + 32 * q) * 8;
            float4 a4 = *(const float4*)wp;
            float4 b4 = *(const float4*)(wp + 4);
            w[q][0] = a4.x; w[q][1] = a4.y; w[q][2] = a4.z; w[q][3] = a4.w;
            w[q][4] = b4.x; w[q][5] = b4.y; w[q][6] = b4.z; w[q][7] = b4.w;
        }
        for (int r = 0; r < 16; r++) {
            const int m = wid * 16 + r;
            const float* tr = tile + m * TPAD;
            const float v0 = tr[lane], v1 = tr[lane + 32], v2 = tr[lane + 64], v3 = tr[lane + 96];
            float p[8];
#pragma unroll
            for (int e = 0; e < 8; e++)
                p[e] = v0 * w[0][e] + v1 * w[1][e] + v2 * w[2][e] + v3 * w[3][e];
#pragma unroll
            for (int e = 0; e < 8; e++)
#pragma unroll
                for (int off = 16; off > 0; off >>= 1)
                    p[e] += __shfl_xor_sync(0xffffffffu, p[e], off);
            if (lane == 0) {
                float* gl = g_logits + (size_t)(bm * 128 + m) * 17 + jb;
#pragma unroll
                for (int e = 0; e < 8; e++) atomicAdd(gl + e, p[e]);
            }
        }
    }
}

// ---------------- flag borderline tokens ----------------
__global__ void flag_kernel() {
    const int t = blockIdx.x * blockDim.x + threadIdx.x;
    if (t >= T_TOK) return;
    const float* l = g_logits + t * 17;
    const float l0 = l[0];
    bool flag = fabsf(l0) < TAU;
    const bool mask = l0 > 0.f;
    float lg[NEXP];
#pragma unroll
    for (int e = 0; e < NEXP; e++) lg[e] = mask ? l[1 + e] : l[9 + e];
    float v1 = -1e30f, v2 = -1e30f, v3 = -1e30f;
#pragma unroll
    for (int e = 0; e < NEXP; e++) {
        float v = lg[e];
        if (v > v1)      { v3 = v2; v2 = v1; v1 = v; }
        else if (v > v2) { v3 = v2; v2 = v; }
        else if (v > v3) { v3 = v; }
    }
    if (v1 - v2 < TAU || v2 - v3 < TAU) flag = true;
    if (flag) {
        int idx = atomicAdd(&g_fix_count, 1);
        if (idx < MAXFIX) { g_fix_list[idx] = t; g_fix_idx[t] = idx; }
    }
}

// ---------------- fixup phase A: k-split partial dots ----------------
__global__ void fixup1a_kernel(const float* __restrict__ X,
                               const float* __restrict__ Wi1,
                               const float* __restrict__ Wr1,
                               const float* __restrict__ Wu1) {
    const int fi = blockIdx.x;
    int cnt = g_fix_count; if (cnt > MAXFIX) cnt = MAXFIX;
    if (fi >= cnt) return;
    const int t = g_fix_list[fi];
    const int kz = blockIdx.z;
    const int kbase = kz * KSEG;
    const int n = blockIdx.y * 256 + threadIdx.x;

    __shared__ float xs[KSEG];
    xs[threadIdx.x] = X[(size_t)t * HDIM + kbase + threadIdx.x];
    __syncthreads();

    const float* W; int nl, ld;
    if (n < 1024)      { W = Wi1; nl = n;        ld = 1024; }
    else if (n < 3072) { W = Wr1; nl = n - 1024; ld = 2048; }
    else               { W = Wu1; nl = n - 3072; ld = 2048; }

    const float* Wp = W + (size_t)kbase * ld + nl;
    float a0 = 0.f, a1 = 0.f, a2 = 0.f, a3 = 0.f;
#pragma unroll 4
    for (int kk = 0; kk < KSEG; kk += 4) {
        a0 = fmaf(xs[kk],     Wp[(size_t)kk * ld],       a0);
        a1 = fmaf(xs[kk + 1], Wp[(size_t)(kk + 1) * ld], a1);
        a2 = fmaf(xs[kk + 2], Wp[(size_t)(kk + 2) * ld], a2);
        a3 = fmaf(xs[kk + 3], Wp[(size_t)(kk + 3) * ld], a3);
    }
    g_fixh[((size_t)fi * KSPLIT + kz) * NHID + n] = ((a0 + a1) + (a2 + a3));
}

// ---------------- fixup phase B: reduce k-partials, relu, layer-2 partials ----------------
__global__ void fixup1b_kernel(const float* __restrict__ bi1,
                               const float* __restrict__ br1,
                               const float* __restrict__ bu1,
                               const float* __restrict__ Wi2,
                               const float* __restrict__ Wr2,
                               const float* __restrict__ Wu2) {
    const int fi = blockIdx.x;
    int cnt = g_fix_count; if (cnt > MAXFIX) cnt = MAXFIX;
    if (fi >= cnt) return;
    const int n = blockIdx.y * 256 + threadIdx.x;
    __shared__ float red[17][257];

    float acc = 0.f;
#pragma unroll
    for (int kz = 0; kz < KSPLIT; kz++)
        acc += g_fixh[((size_t)fi * KSPLIT + kz) * NHID + n];

    const float* b; int nl;
    if (n < 1024)      { b = bi1; nl = n; }
    else if (n < 3072) { b = br1; nl = n - 1024; }
    else               { b = bu1; nl = n - 3072; }
    const float hval = fmaxf(acc + b[nl], 0.f);

    float part[17];
#pragma unroll
    for (int j = 0; j < 17; j++) part[j] = 0.f;
    if (n < 1024) part[0] = hval * Wi2[n];
    else if (n < 3072) {
        const float* w = Wr2 + (size_t)(n - 1024) * 8;
#pragma unroll
        for (int e = 0; e < NEXP; e++) part[1 + e] = hval * w[e];
    } else {
        const float* w = Wu2 + (size_t)(n - 3072) * 8;
#pragma unroll
        for (int e = 0; e < NEXP; e++) part[9 + e] = hval * w[e];
    }
#pragma unroll
    for (int j = 0; j < 17; j++) red[j][threadIdx.x] = part[j];
    __syncthreads();
    for (int s = 128; s > 0; s >>= 1) {
        if (threadIdx.x < s)
#pragma unroll
            for (int j = 0; j < 17; j++) red[j][threadIdx.x] += red[j][threadIdx.x + s];
        __syncthreads();
    }
    if (threadIdx.x < 17)
        g_fix_part[(fi * 20 + blockIdx.y) * 17 + threadIdx.x] = red[threadIdx.x][0];
}

// ---------------- fused: fixup2 + router + scatter + finalize ----------------
__global__ void router_fused_kernel(float* __restrict__ out,
                                    const float* __restrict__ bi2,
                                    const float* __restrict__ br2,
                                    const float* __restrict__ bu2) {
    const int tid = threadIdx.x;
    const int t = blockIdx.x * 256 + tid;

    float l[17];
    const int fidx = g_fix_idx[t];
    if (fidx >= 0) {
#pragma unroll
        for (int j = 0; j < 17; j++) {
            float s = 0.f;
            for (int p = 0; p < 20; p++) s += g_fix_part[(fidx * 20 + p) * 17 + j];
            l[j] = s + ((j == 0) ? bi2[0] : (j < 9 ? br2[j - 1] : bu2[j - 9]));
        }
    } else {
#pragma unroll
        for (int j = 0; j < 17; j++) l[j] = g_logits[t * 17 + j];
    }

    const float imp = 1.f / (1.f + expf(-l[0]));
    out[IMP_OFF + t] = imp;
    const bool mask = imp > 0.5f;
    float lg[NEXP];
#pragma unroll
    for (int e = 0; e < NEXP; e++) lg[e] = mask ? l[1 + e] : l[9 + e];
    float m = lg[0];
#pragma unroll
    for (int e = 1; e < NEXP; e++) m = fmaxf(m, lg[e]);
    float p[NEXP], s = 0.f;
#pragma unroll
    for (int e = 0; e < NEXP; e++) { p[e] = expf(lg[e] - m); s += p[e]; }
#pragma unroll
    for (int e = 0; e < NEXP; e++) {
        p[e] = p[e] / s;
        out[PROB_OFF + (size_t)t * NEXP + e] = p[e];
    }
    int i0 = 0; float p0 = p[0];
#pragma unroll
    for (int e = 1; e < NEXP; e++) if (p[e] > p0) { p0 = p[e]; i0 = e; }
    int i1 = -1; float p1 = -1.f;
#pragma unroll
    for (int e = 0; e < NEXP; e++) if (e != i0 && p[e] > p1) { p1 = p[e]; i1 = e; }
    const float sn = p0 + p1;
    atomicOr(&g_occ0, 1 << i0);

    __threadfence();
    __syncthreads();
    if (tid == 0) {
        atomicAdd(&g_bar, 1);
        while (atomicAdd(&g_bar, 0) < (int)gridDim.x) { }
    }
    __syncthreads();

    const int occ = *(volatile int*)&g_occ0;
    size_t b0 = (size_t)(t * NEXP + i0) * CAP;
    out[DISP_OFF + b0] = 1.f;
    out[COMB_OFF + b0] = p0 / sn;
    const int pos1 = (occ >> i1) & 1;
    size_t b1 = (size_t)(t * NEXP + i1) * CAP + pos1;
    out[DISP_OFF + b1] = 1.f;
    out[COMB_OFF + b1] = p1 / sn;

    if (blockIdx.x == 0) {
        __shared__ float sr[NEXP][256];
        __shared__ float si[NEXP][256];
        float rl[NEXP], il[NEXP];
#pragma unroll
        for (int e = 0; e < NEXP; e++) { rl[e] = 0.f; il[e] = 0.f; }
        for (int tt = tid; tt < T_TOK; tt += 256) {
            const float mv = out[IMP_OFF + tt] > 0.5f ? 1.f : 0.f;
#pragma unroll
            for (int e = 0; e < NEXP; e++) {
                const float pe = out[PROB_OFF + (size_t)tt * NEXP + e];
                rl[e] += pe; il[e] += pe * mv;
            }
        }
#pragma unroll
        for (int e = 0; e < NEXP; e++) { sr[e][tid] = rl[e]; si[e][tid] = il[e]; }
        __syncthreads();
        for (int st2 = 128; st2 > 0; st2 >>= 1) {
            if (tid < st2)
#pragma unroll
                for (int e = 0; e < NEXP; e++) { sr[e][tid] += sr[e][tid + st2]; si[e][tid] += si[e][tid + st2]; }
            __syncthreads();
        }
        if (tid == 0) {
            const float EPS = 1e-9f;
            float ent = 0.f, imp_sum[NEXP], tot = 0.f;
#pragma unroll
            for (int e = 0; e < NEXP; e++) {
                const float rppe = sr[e][0] / (float)T_TOK;
                ent += rppe * logf(rppe * (float)NEXP + EPS);
                imp_sum[e] = si[e][0] + EPS; tot += imp_sum[e];
            }
            float ih = 0.f;
#pragma unroll
            for (int e = 0; e < NEXP; e++) {
                const float ipe = imp_sum[e] / tot;
                ih -= ipe * logf(ipe + EPS);
            }
            out[AUX_OFF] = ent - 0.1f * (ih / logf((float)NEXP));
        }
    }
}

// ---------------- launch ----------------
extern "C" void kernel_launch(void* const* d_in, const int* in_sizes, int n_in,
                              void* d_out, int out_size) {
    const float* x   = (const float*)d_in[0];
    const float* Wi1 = (const float*)d_in[1];
    const float* bi1 = (const float*)d_in[2];
    const float* Wi2 = (const float*)d_in[3];
    const float* bi2 = (const float*)d_in[4];
    const float* Wr1 = (const float*)d_in[5];
    const float* br1 = (const float*)d_in[6];
    const float* Wr2 = (const float*)d_in[7];
    const float* br2 = (const float*)d_in[8];
    const float* Wu1 = (const float*)d_in[9];
    const float* bu1 = (const float*)d_in[10];
    const float* Wu2 = (const float*)d_in[11];
    const float* bu2 = (const float*)d_in[12];
    float* out = (float*)d_out;

    cudaFuncSetAttribute(gemm1_mma_kernel, cudaFuncAttributeMaxDynamicSharedMemorySize, SMEM_GEMM);

    prep_kernel<<<PREP_GRID, 256>>>((const float4*)x, Wi1, Wr1, Wu1, bi2, br2, bu2);
    gemm1_mma_kernel<<<dim3(NHID / 128, T_TOK / 128), 256, SMEM_GEMM>>>(bi1, br1, bu1, Wi2, Wr2, Wu2, (float4*)out);
    flag_kernel<<<T_TOK / 256, 256>>>();
    fixup1a_kernel<<<dim3(MAXFIX, 20, KSPLIT), 256>>>(x, Wi1, Wr1, Wu1);
    fixup1b_kernel<<<dim3(MAXFIX, 20), 256>>>(bi1, br1, bu1, Wi2, Wr2, Wu2);
    router_fused_kernel<<<T_TOK / 256, 256>>>(out, bi2, br2, bu2);
}